// round 14
// baseline (speedup 1.0000x reference)
#include <cuda_runtime.h>
#include <cuda_fp16.h>
#include <cstdint>

typedef unsigned long long ull;

#define Bz   16
#define EMB  300
#define AH   256
#define KPADR 832              // padded 812 -> 832 (26*32)
#define NR   768               // 3*256
#define MR   16384
#define RNNK 1280
#define NG   1024
#define HH   128

// ---- scratch: split fp16, INTERLEAVED-32 storage: [hi(0:32)|lo(0:32)|hi(32:64)|lo...] ----
// row length = 2*K halves. 3-pass GEMM: Ah*Bh + Al*Bh + Ah*Bl (exact split);
// 2-pass GEMM drops Ah*Bl.
__device__ __half g_A3 [MR * (2*KPADR)];        // 16384 x 1664
__device__ __half g_W3 [NR * (2*KPADR)];        // 768 x 1664
__device__ float  g_vbig[NR];
__device__ __half g_R3A[8192 * (2*NR)];         // x1 rows: 8192 x 1536
__device__ __half g_R3B[8192 * (2*NR)];         // x2 rows (v-scaled)
__device__ float  g_S  [48 * 512 * 512];
__device__ __half g_AL3[48 * 512 * 1024];       // alpha, rows (b*3+i)*512+l
__device__ __half g_X2T3[48 * 256 * 1024];      // x2^T, rows (i*16+b)*256+d
__device__ __half g_X13[8192 * (2*RNNK)];       // X1CAT, 8192 x 2560
__device__ __half g_Wih3[NG * (2*RNNK)];        // 1024 x 2560
__device__ float  g_bias[NG];
__device__ float  g_G  [8192 * NG];
__device__ uint2  g_WhhH[2 * 32 * 512];         // [dir][k4][thread]: 2x half2 (fp16 Whh, shuffled gate map)

// ---- helpers ----
__device__ __forceinline__ uint32_t s2u(const void* p) {
    uint32_t a;
    asm("{ .reg .u64 t; cvta.to.shared.u64 t, %1; cvt.u32.u64 %0, t; }" : "=r"(a) : "l"(p));
    return a;
}
__device__ __forceinline__ void split_h(float v, __half& h, __half& l) {
    h = __float2half_rn(v);
    l = __float2half_rn(v - __half2float(h));
}
__device__ __forceinline__ int coff(int c) {        // interleaved-32 column map (hi; lo = +32)
    return ((c >> 5) << 6) + (c & 31);
}
__device__ __forceinline__ uint32_t swz(uint32_t off) {
    return off ^ ((off >> 3) & 0x70);
}
__device__ __forceinline__ void cp16(uint32_t dst, const void* src) {
    asm volatile("cp.async.cg.shared.global [%0], [%1], 16;" :: "r"(dst), "l"(src));
}
__device__ __forceinline__ void ldm_x4(uint32_t* r, uint32_t addr) {
    asm volatile("ldmatrix.sync.aligned.m8n8.x4.shared.b16 {%0,%1,%2,%3}, [%4];"
                 : "=r"(r[0]), "=r"(r[1]), "=r"(r[2]), "=r"(r[3]) : "r"(addr));
}
__device__ __forceinline__ void mma16816(float* c, const uint32_t* a, const uint32_t* b) {
    asm volatile(
        "mma.sync.aligned.m16n8k16.row.col.f32.f16.f16.f32 "
        "{%0,%1,%2,%3}, {%4,%5,%6,%7}, {%8,%9}, {%0,%1,%2,%3};"
        : "+f"(c[0]), "+f"(c[1]), "+f"(c[2]), "+f"(c[3])
        : "r"(a[0]), "r"(a[1]), "r"(a[2]), "r"(a[3]), "r"(b[0]), "r"(b[1]));
}
__device__ __forceinline__ __half2 u2h2(uint32_t u) {
    __half2 h; asm("mov.b32 %0, %1;" : "=r"(*(uint32_t*)&h) : "r"(u)); return h;
}

// ---------------- prep kernels ----------------
__global__ void prep_A3(const float* __restrict__ x1w, const float* __restrict__ x1a0,
                        const float* __restrict__ x1a1, const float* __restrict__ x2w,
                        const float* __restrict__ x2a0, const float* __restrict__ x2a1) {
    int idx = blockIdx.x * 256 + threadIdx.x;
    if (idx >= MR * KPADR) return;
    int r = idx / KPADR, c = idx - r * KPADR;
    float v = 0.f;
    if (c < 812) {
        int half = r >> 13, bl = r & 8191;
        if (c < 300)       v = (half ? x2w  : x1w )[(size_t)bl * EMB + c];
        else if (c < 556)  v = (half ? x2a0 : x1a0)[(size_t)bl * AH + (c - 300)];
        else               v = (half ? x2a1 : x1a1)[(size_t)bl * AH + (c - 556)];
    }
    __half h, l; split_h(v, h, l);
    __half* p = g_A3 + (size_t)r * (2 * KPADR) + coff(c);
    p[0] = h; p[32] = l;
}

__global__ void prep_W3(const float* __restrict__ Wattn, const float* __restrict__ vattn) {
    int idx = blockIdx.x * 256 + threadIdx.x;
    if (idx >= NR * KPADR) return;
    int g = idx / KPADR, c = idx - g * KPADR;
    int i = g >> 8, a = g & 255;
    float v = (a < 250 && c < 812) ? Wattn[((size_t)(i * 250 + a)) * 812 + c] : 0.f;
    __half h, l; split_h(v, h, l);
    __half* p = g_W3 + (size_t)g * (2 * KPADR) + coff(c);
    p[0] = h; p[32] = l;
    if (idx < NR) {
        int i2 = idx >> 8, a2 = idx & 255;
        g_vbig[idx] = (a2 < 250) ? vattn[i2 * 250 + a2] : 0.f;
    }
}

__global__ void prep_Wih3(const float* __restrict__ Wf, const float* __restrict__ Wb,
                          const float* __restrict__ bf, const float* __restrict__ bb) {
    int idx = blockIdx.x * 256 + threadIdx.x;
    if (idx >= NG * RNNK) return;
    int r = idx / RNNK, c = idx - r * RNNK;
    float v = (r < 512) ? Wf[(size_t)r * RNNK + c] : Wb[(size_t)(r - 512) * RNNK + c];
    __half h, l; split_h(v, h, l);
    __half* p = g_Wih3 + (size_t)r * (2 * RNNK) + coff(c);
    p[0] = h; p[32] = l;
    if (idx < NG) g_bias[idx] = (idx < 512) ? bf[idx] : bb[idx - 512];
}

__global__ void prep_headX13(const float* __restrict__ x1a0, const float* __restrict__ x1a1) {
    int idx = blockIdx.x * 256 + threadIdx.x;
    if (idx >= 8192 * 512) return;
    int r = idx >> 9, c = idx & 511;
    float v = (c < 256) ? x1a0[(size_t)r * AH + c] : x1a1[(size_t)r * AH + (c - 256)];
    __half h, l; split_h(v, h, l);
    __half* p = g_X13 + (size_t)r * (2 * RNNK) + coff(c);
    p[0] = h; p[32] = l;
}

// transpose x2_abstr_i [b][s][d] -> X2T3 rows (i*16+b)*256+d, cols s (interleaved-32)
__global__ void prep_X2T3(const float* __restrict__ a0, const float* __restrict__ a1,
                          const float* __restrict__ a2) {
    __shared__ float tile[32][33];
    int i = blockIdx.z >> 4, b = blockIdx.z & 15;
    int s0 = blockIdx.x * 32, d0 = blockIdx.y * 32;
    int tx = threadIdx.x, ty = threadIdx.y;
    const float* src = (i == 0) ? a0 : (i == 1) ? a1 : a2;
    tile[ty][tx] = src[((size_t)(b * 512 + s0 + ty)) * 256 + d0 + tx];
    __syncthreads();
    float v = tile[tx][ty];
    __half h, l; split_h(v, h, l);
    __half* p = g_X2T3 + ((size_t)((i * 16 + b) * 256 + d0 + ty)) * 1024 + s0 * 2 + tx;
    p[0] = h; p[32] = l;
}

// fp16 Whh with shuffled gate->thread map: thread t (w=t>>5, l=t&31):
//   unit u = 8*w + (l&7), gate type gt = l>>3, conventional row = gt*128 + u
__global__ void prep_WhhH(const float* __restrict__ Whhf, const float* __restrict__ Whhb) {
    int idx = blockIdx.x * 256 + threadIdx.x;
    if (idx >= 2 * 32 * 512) return;
    int d = idx >> 14, k4 = (idx >> 9) & 31, t = idx & 511;
    int w = t >> 5, l = t & 31;
    int grow = (l >> 3) * 128 + 8 * w + (l & 7);
    const float* s = d ? Whhb : Whhf;
    size_t base = (size_t)grow * HH + k4 * 4;
    __half2 p0 = __floats2half2_rn(s[base],     s[base + 1]);
    __half2 p1 = __floats2half2_rn(s[base + 2], s[base + 3]);
    uint2 u;
    u.x = *(uint32_t*)&p0;
    u.y = *(uint32_t*)&p1;
    g_WhhH[idx] = u;
}

// ---------------- HMMA GEMM: grid-per-tile, split fp16, interleaved-32 storage --------
// Chunk = 32 base cols = one 128B smem row slice (hi|lo). Stage 32KB, 3 stages, 2 CTA/SM.
// NPASS=3: Ah*Bh + Al*Bh + Ah*Bl (exact).  NPASS=2: drops Ah*Bl.
// EPI: 0 scores f32 | 1 R split-out relu(+v) | 2 gin f32+bias | 3 X13 split-out
#define HG_STAGE 32768
#define HG_SMEM  (3 * HG_STAGE)

template <int EPI, int NPASS>
__global__ void __launch_bounds__(256, 2)
hgemm(const __half* __restrict__ A, const __half* __restrict__ B,
      float* __restrict__ Cf, __half* __restrict__ Cb,
      int ldA, int ldB, int ldC, int nkc,
      int zdiv, long sAb, long sAi, long sBb, long sBi, long sCb, long sCi,
      const float* __restrict__ evec, int rowSplit) {
    extern __shared__ __align__(1024) char smem[];
    const uint32_t su = s2u(smem);
    const int tid = threadIdx.x, lane = tid & 31, wid = tid >> 5;

    const int z = blockIdx.z, zi = z % zdiv, zb = z / zdiv;
    A += zb * sAb + zi * sAi;
    B += zb * sBb + zi * sBi;
    if (EPI == 0 || EPI == 2) Cf += zb * sCb + zi * sCi;
    if (EPI == 3)             Cb += zb * sCb + zi * sCi;
    const int m0 = blockIdx.y * 128, n0 = blockIdx.x * 128;
    const int r0 = tid >> 3, c16 = tid & 7;

    float acc[2][8][4];
#pragma unroll
    for (int i = 0; i < 2; i++)
#pragma unroll
        for (int j = 0; j < 8; j++)
#pragma unroll
            for (int q = 0; q < 4; q++) acc[i][j][q] = 0.f;

    const int wm = wid & 3, wn = wid >> 2;
    const int a_row = wm * 32 + (lane & 15);
    const int a_kb  = (lane >> 4) * 8;           // halves
    const int b_row = wn * 64 + ((lane >> 4) << 3) + (lane & 7);
    const int b_kb  = ((lane >> 3) & 1) * 8;     // halves

    // issue chunk kc (32 base cols = 64 storage halves = 128B row) into stage st
    auto issue = [&](int kc, int st) {
        const __half* Ag = A + (size_t)(m0 + r0) * ldA + kc * 64 + c16 * 8;
        const __half* Bg = B + (size_t)(n0 + r0) * ldB + kc * 64 + c16 * 8;
        uint32_t sb = su + st * HG_STAGE;
#pragma unroll
        for (int j = 0; j < 4; ++j) {
            uint32_t off = swz((r0 + 32 * j) * 128 + c16 * 16);
            cp16(sb + off,          Ag + (size_t)(32 * j) * ldA);
            cp16(sb + 16384 + off,  Bg + (size_t)(32 * j) * ldB);
        }
        asm volatile("cp.async.commit_group;" ::: "memory");
    };

    issue(0, 0);
    issue(1, 1);
    for (int kc = 0; kc < nkc; ++kc) {
        const int st = kc % 3;
        if (kc == nkc - 1)
            asm volatile("cp.async.wait_group 0;" ::: "memory");  // last chunk IS the newest group
        else
            asm volatile("cp.async.wait_group 1;" ::: "memory");
        __syncthreads();
        if (kc + 2 < nkc) issue(kc + 2, (kc + 2) % 3);
        const uint32_t sA = su + st * HG_STAGE;
        const uint32_t sB = sA + 16384;
#pragma unroll
        for (int s = 0; s < 2; ++s) {
            const uint32_t aH0 = (uint32_t)(a_row)      * 128 + (s * 16 + a_kb) * 2;
            const uint32_t aH1 = (uint32_t)(a_row + 16) * 128 + (s * 16 + a_kb) * 2;
            uint32_t ah[2][4], al[2][4], bb[4][4];
            ldm_x4(ah[0], sA + swz(aH0));
            ldm_x4(ah[1], sA + swz(aH1));
#pragma unroll
            for (int nj = 0; nj < 4; ++nj) {
                uint32_t off = (uint32_t)(b_row + nj * 16) * 128 + (s * 16 + b_kb) * 2;
                ldm_x4(bb[nj], sB + swz(off));
            }
            // pass 1: Ah * Bh
#pragma unroll
            for (int mi = 0; mi < 2; ++mi)
#pragma unroll
                for (int ni = 0; ni < 8; ++ni)
                    mma16816(acc[mi][ni], ah[mi], &bb[ni >> 1][(ni & 1) * 2]);
            // pass 2: Al * Bh
            ldm_x4(al[0], sA + swz(aH0 + 64));
            ldm_x4(al[1], sA + swz(aH1 + 64));
#pragma unroll
            for (int mi = 0; mi < 2; ++mi)
#pragma unroll
                for (int ni = 0; ni < 8; ++ni)
                    mma16816(acc[mi][ni], al[mi], &bb[ni >> 1][(ni & 1) * 2]);
            // pass 3: Ah * Bl (reuse bb regs) — exact mode only
            if (NPASS == 3) {
#pragma unroll
                for (int nj = 0; nj < 4; ++nj) {
                    uint32_t off = (uint32_t)(b_row + nj * 16) * 128 + (s * 16 + b_kb) * 2 + 64;
                    ldm_x4(bb[nj], sB + swz(off));
                }
#pragma unroll
                for (int mi = 0; mi < 2; ++mi)
#pragma unroll
                    for (int ni = 0; ni < 8; ++ni)
                        mma16816(acc[mi][ni], ah[mi], &bb[ni >> 1][(ni & 1) * 2]);
            }
        }
    }

    const int tq = lane >> 2, tr = (lane & 3) * 2;
#pragma unroll
    for (int mi = 0; mi < 2; ++mi) {
#pragma unroll
        for (int h = 0; h < 2; ++h) {
            const int mg = m0 + wm * 32 + mi * 16 + h * 8 + tq;
#pragma unroll
            for (int ni = 0; ni < 8; ++ni) {
                const int nc = n0 + wn * 64 + ni * 8 + tr;
                float v0 = acc[mi][ni][h * 2], v1 = acc[mi][ni][h * 2 + 1];
                if (EPI == 0) {
                    *(float2*)(Cf + (size_t)mg * ldC + nc) = make_float2(v0, v1);
                } else if (EPI == 2) {
                    *(float2*)(Cf + (size_t)mg * ldC + nc) =
                        make_float2(v0 + evec[nc], v1 + evec[nc + 1]);
                } else if (EPI == 1) {
                    const bool isB = (mg >= rowSplit);
                    v0 = fmaxf(v0, 0.f); v1 = fmaxf(v1, 0.f);
                    if (isB) { v0 *= evec[nc]; v1 *= evec[nc + 1]; }
                    __half h0, l0, h1, l1;
                    split_h(v0, h0, l0); split_h(v1, h1, l1);
                    __half* p = (isB ? g_R3B + (size_t)(mg - rowSplit) * (2 * NR)
                                     : g_R3A + (size_t)mg * (2 * NR)) + coff(nc);
                    *(__half2*)(p)      = __halves2half2(h0, h1);
                    *(__half2*)(p + 32) = __halves2half2(l0, l1);
                } else {  // EPI == 3
                    __half h0, l0, h1, l1;
                    split_h(v0, h0, l0); split_h(v1, h1, l1);
                    __half* p = Cb + (size_t)mg * (2 * RNNK) + coff(nc);
                    *(__half2*)(p)      = __halves2half2(h0, h1);
                    *(__half2*)(p + 32) = __halves2half2(l0, l1);
                }
            }
        }
    }
}

// ---------------- softmax: rows of 512 -> split fp16 alpha (interleaved-32) ----------------
__global__ void softmax_kernel(const float* __restrict__ S, const unsigned char* __restrict__ x2mask) {
    const float NEGF = -3.4e38f;
    const float2* row = (const float2*)(S + (size_t)blockIdx.x * 512);
    int b = blockIdx.x / 1536;
    const unsigned char* mk = x2mask + b * 512;
    int t = threadIdx.x;
    float2 v = row[t];
    if (mk[2 * t])     v.x = NEGF;
    if (mk[2 * t + 1]) v.y = NEGF;
    __shared__ float red[8];
    float mx = fmaxf(v.x, v.y);
#pragma unroll
    for (int o = 16; o; o >>= 1) mx = fmaxf(mx, __shfl_xor_sync(0xffffffffu, mx, o));
    if ((t & 31) == 0) red[t >> 5] = mx;
    __syncthreads();
    float M = red[0];
#pragma unroll
    for (int i = 1; i < 8; i++) M = fmaxf(M, red[i]);
    __syncthreads();
    float e0 = __expf(v.x - M), e1 = __expf(v.y - M);
    float s = e0 + e1;
#pragma unroll
    for (int o = 16; o; o >>= 1) s += __shfl_xor_sync(0xffffffffu, s, o);
    if ((t & 31) == 0) red[t >> 5] = s;
    __syncthreads();
    float tot = red[0];
#pragma unroll
    for (int i = 1; i < 8; i++) tot += red[i];
    float inv = __fdividef(1.f, tot);
    float p0 = e0 * inv, p1 = e1 * inv;
    __half h0, l0, h1, l1;
    split_h(p0, h0, l0); split_h(p1, h1, l1);
    __half* p = g_AL3 + (size_t)blockIdx.x * 1024 + coff(2 * t);
    *(__half2*)(p)      = __halves2half2(h0, h1);
    *(__half2*)(p + 32) = __halves2half2(l0, l1);
}

// ---------------- BiLSTM: fp16 Whh, warp-gathered gates, 1 barrier/step ----------------
// Thread t: warp w=t>>5, lane l=t&31; unit u = 8w+(l&7); gate type gt = l>>3 (i,f,g,o).
// Each thread computes its gate's z over all 128 h; the unit's 4 z's are gathered with
// 3 intra-warp shuffles; lanes gt==0 update c,h and store h into a double-buffered vector.
__device__ __forceinline__ float sigf(float x) { return __fdividef(1.f, 1.f + __expf(-x)); }
__device__ __forceinline__ float tanhf_fast(float x) { return 1.f - __fdividef(2.f, __expf(2.f * x) + 1.f); }

#define LSTM_SMEM (16 * 512 * 8 + 2 * 128 * 2)   // Ws 64KB + double-buffered h (512B)

__global__ void __launch_bounds__(512, 1)
lstm_kernel(const float* __restrict__ G, float* __restrict__ out) {
    extern __shared__ char smraw[];
    uint2*  Ws  = (uint2*)smraw;                     // [k4 0..15][512]
    __half* hsH = (__half*)(smraw + 16 * 512 * 8);   // [2][128]

    const int dir = blockIdx.x & 1;
    const int b   = blockIdx.x >> 1;
    const int t   = threadIdx.x;
    const int w   = t >> 5, l = t & 31;
    const int u   = 8 * w + (l & 7);
    const int gt  = l >> 3;
    const int grow = gt * 128 + u;
    const int lsrc = l & 7;                          // base lane of this unit's gate-i thread

    const uint2* Wg = g_WhhH + (size_t)dir * 32 * 512;
    for (int i = t; i < 16 * 512; i += 512) Ws[i] = Wg[i];
    uint2 wr[16];
#pragma unroll
    for (int j = 0; j < 16; j++) wr[j] = Wg[(16 + j) * 512 + t];
    if (t < 128) hsH[t] = __float2half(0.f);         // buffer 0 = h_0 = 0
    float c = 0.f;
    __syncthreads();

    const float* gptr = G + (size_t)b * 512 * NG + dir * 512 + grow;
    int trow = dir ? 511 : 0;
    const int tstep = dir ? -1 : 1;
    float gv = gptr[(size_t)trow * NG];

    const __half2 z2 = __floats2half2_rn(0.f, 0.f);

    for (int st = 0; st < 512; ++st) {
        float gcur = gv;
        if (st + 1 < 512) gv = gptr[(size_t)(trow + tstep) * NG];

        const int rb = st & 1;                       // read buffer
        uint4 hu[16];
        const uint4* hp = (const uint4*)(hsH + rb * 128);
#pragma unroll
        for (int j = 0; j < 16; j++) hu[j] = hp[j];

        __half2 accA[4] = {z2, z2, z2, z2};
        __half2 accB[4] = {z2, z2, z2, z2};
#pragma unroll
        for (int k4 = 0; k4 < 16; k4++) {
            uint2 wv = Ws[k4 * 512 + t];
            uint4 h4 = hu[k4 >> 1];
            uint32_t ha = (k4 & 1) ? h4.z : h4.x;
            uint32_t hb = (k4 & 1) ? h4.w : h4.y;
            accA[k4 & 3] = __hfma2(u2h2(wv.x), u2h2(ha), accA[k4 & 3]);
            accB[k4 & 3] = __hfma2(u2h2(wv.y), u2h2(hb), accB[k4 & 3]);
        }
#pragma unroll
        for (int j = 0; j < 16; j++) {
            int k4 = 16 + j;
            uint2 wv = wr[j];
            uint4 h4 = hu[k4 >> 1];
            uint32_t ha = (k4 & 1) ? h4.z : h4.x;
            uint32_t hb = (k4 & 1) ? h4.w : h4.y;
            accA[j & 3] = __hfma2(u2h2(wv.x), u2h2(ha), accA[j & 3]);
            accB[j & 3] = __hfma2(u2h2(wv.y), u2h2(hb), accB[j & 3]);
        }
        float zsum = 0.f;
#pragma unroll
        for (int j = 0; j < 4; j++) {
            float2 fa = __half22float2(accA[j]);
            float2 fb = __half22float2(accB[j]);
            zsum += (fa.x + fa.y) + (fb.x + fb.y);
        }
        const float zme = zsum + gcur;

        // gather the unit's f,g,o gate values into the gate-i thread (3 shuffles)
        const float zf = __shfl_sync(0xffffffffu, zme, lsrc + 8);
        const float zg = __shfl_sync(0xffffffffu, zme, lsrc + 16);
        const float zo = __shfl_sync(0xffffffffu, zme, lsrc + 24);

        if (gt == 0) {
            c = sigf(zf) * c + sigf(zme) * tanhf_fast(zg);
            float h = sigf(zo) * tanhf_fast(c);
            hsH[(rb ^ 1) * 128 + u] = __float2half_rn(h);
            out[((size_t)b * 512 + trow) * 256 + dir * 128 + u] = h;
        }
        __syncthreads();
        trow += tstep;
    }
}

// ---------------- launch ----------------
extern "C" void kernel_launch(void* const* d_in, const int* in_sizes, int n_in,
                              void* d_out, int out_size) {
    const float* x1w  = (const float*)d_in[0];
    const float* x1a0 = (const float*)d_in[1];
    const float* x1a1 = (const float*)d_in[2];
    const float* x2w  = (const float*)d_in[3];
    const float* x2a0 = (const float*)d_in[4];
    const float* x2a1 = (const float*)d_in[5];
    const float* x2a2 = (const float*)d_in[6];
    const unsigned char* x2mask = (const unsigned char*)d_in[8];
    const float* Wattn = (const float*)d_in[9];
    const float* vattn = (const float*)d_in[10];
    const float* Wihf = (const float*)d_in[11];
    const float* Whhf = (const float*)d_in[12];
    const float* bf   = (const float*)d_in[13];
    const float* Wihb = (const float*)d_in[14];
    const float* Whhb = (const float*)d_in[15];
    const float* bb   = (const float*)d_in[16];
    float* out = (float*)d_out;

    static bool attr_done = false;
    if (!attr_done) {
        cudaFuncSetAttribute(lstm_kernel, cudaFuncAttributeMaxDynamicSharedMemorySize, LSTM_SMEM);
        cudaFuncSetAttribute((const void*)hgemm<0,3>, cudaFuncAttributeMaxDynamicSharedMemorySize, HG_SMEM);
        cudaFuncSetAttribute((const void*)hgemm<1,3>, cudaFuncAttributeMaxDynamicSharedMemorySize, HG_SMEM);
        cudaFuncSetAttribute((const void*)hgemm<2,2>, cudaFuncAttributeMaxDynamicSharedMemorySize, HG_SMEM);
        cudaFuncSetAttribute((const void*)hgemm<3,2>, cudaFuncAttributeMaxDynamicSharedMemorySize, HG_SMEM);
        attr_done = true;
    }

    __half *A3, *W3, *R3A, *R3B, *AL3, *X2T3, *X13, *Wih3;
    float *vbig, *S, *bias, *Gm;
    cudaGetSymbolAddress((void**)&A3,   g_A3);
    cudaGetSymbolAddress((void**)&W3,   g_W3);
    cudaGetSymbolAddress((void**)&vbig, g_vbig);
    cudaGetSymbolAddress((void**)&R3A,  g_R3A);
    cudaGetSymbolAddress((void**)&R3B,  g_R3B);
    cudaGetSymbolAddress((void**)&S,    g_S);
    cudaGetSymbolAddress((void**)&AL3,  g_AL3);
    cudaGetSymbolAddress((void**)&X2T3, g_X2T3);
    cudaGetSymbolAddress((void**)&X13,  g_X13);
    cudaGetSymbolAddress((void**)&Wih3, g_Wih3);
    cudaGetSymbolAddress((void**)&bias, g_bias);
    cudaGetSymbolAddress((void**)&Gm,   g_G);

    // launches 0..2, then the R GEMM at index 3 (ncu profiles launch 3)
    prep_A3  <<<(MR * KPADR + 255) / 256, 256>>>(x1w, x1a0, x1a1, x2w, x2a0, x2a1);
    prep_W3  <<<(NR * KPADR + 255) / 256, 256>>>(Wattn, vattn);
    prep_WhhH<<<(2 * 32 * 512 + 255) / 256, 256>>>(Whhf, Whhb);

    // R = relu(A3 * W3^T) (+v for x2 rows): M=16384, N=768, baseK=832 -> 26 chunks, 3-pass
    {
        dim3 grid(6, 128, 1);
        hgemm<1,3><<<grid, 256, HG_SMEM>>>(A3, W3, nullptr, nullptr,
            2 * KPADR, 2 * KPADR, 0, 26,
            1, 0, 0, 0, 0, 0, 0, vbig, 8192);
    }

    prep_Wih3   <<<(NG * RNNK + 255) / 256, 256>>>(Wihf, Wihb, bf, bb);
    prep_headX13<<<(8192 * 512 + 255) / 256, 256>>>(x1a0, x1a1);
    {
        dim3 grid(16, 8, 48), blk(32, 32, 1);
        prep_X2T3<<<grid, blk>>>(x2a0, x2a1, x2a2);
    }

    // scores per (b,i): S = r1 * r2^T: M=512, N=512, baseK=256 -> 8 chunks, 3-pass
    {
        dim3 grid(4, 4, 48);
        hgemm<0,3><<<grid, 256, HG_SMEM>>>(R3A, R3B, S, nullptr,
            2 * NR, 2 * NR, 512, 8,
            3,
            (long)512 * 2 * NR, 512, (long)512 * 2 * NR, 512,
            (long)3 * 512 * 512, (long)512 * 512, nullptr, 0);
    }
    softmax_kernel<<<48 * 512, 256>>>(S, x2mask);
    // attn per (b,i): X13[:, base 512 + i*256 ..] = alpha * x2_i^T: M=512, N=256, baseK=512 -> 16 chunks, 2-pass
    {
        dim3 grid(2, 4, 48);
        hgemm<3,2><<<grid, 256, HG_SMEM>>>(AL3, X2T3, nullptr, X13 + 1024,
            1024, 1024, 0, 16,
            3,
            (long)3 * 512 * 1024, (long)512 * 1024,
            (long)256 * 1024, (long)16 * 256 * 1024,
            (long)512 * 2 * RNNK, 512, nullptr, 0);
    }
    // g_in = X13 * Wih3^T + bias: M=8192, N=1024, baseK=1280 -> 40 chunks, 2-pass
    {
        dim3 grid(8, 64, 1);
        hgemm<2,2><<<grid, 256, HG_SMEM>>>(X13, Wih3, Gm, nullptr,
            2 * RNNK, 2 * RNNK, NG, 40,
            1, 0, 0, 0, 0, 0, 0, bias, 0);
    }
    lstm_kernel<<<32, 512, LSTM_SMEM>>>(Gm, out);
}

// round 15
// speedup vs baseline: 1.0513x; 1.0513x over previous
#include <cuda_runtime.h>
#include <cuda_fp16.h>
#include <cstdint>

typedef unsigned long long ull;

#define Bz   16
#define EMB  300
#define AH   256
#define KPADR 832              // padded 812 -> 832 (26*32)
#define NR   768               // 3*256
#define MR   16384
#define RNNK 1280
#define NG   1024
#define HH   128

// ---- scratch: split fp16, INTERLEAVED-32 storage: [hi(0:32)|lo(0:32)|hi(32:64)|lo...] ----
// row length = 2*K halves. 3-pass GEMM: Ah*Bh + Al*Bh + Ah*Bl (exact split);
// 2-pass GEMM drops Ah*Bl.
__device__ __align__(16) __half g_A3 [MR * (2*KPADR)];   // 16384 x 1664
__device__ __align__(16) __half g_W3 [NR * (2*KPADR)];   // 768 x 1664
__device__ float  g_vbig[NR];
__device__ __align__(16) __half g_R3A[8192 * (2*NR)];    // x1 rows: 8192 x 1536
__device__ __align__(16) __half g_R3B[8192 * (2*NR)];    // x2 rows (v-scaled)
__device__ float  g_S  [48 * 512 * 512];
__device__ __align__(16) __half g_AL3[48 * 512 * 1024];  // alpha, rows (b*3+i)*512+l
__device__ __align__(16) __half g_X2T3[48 * 256 * 1024]; // x2^T, rows (i*16+b)*256+d
__device__ __align__(16) __half g_X13[8192 * (2*RNNK)];  // X1CAT, 8192 x 2560
__device__ __align__(16) __half g_Wih3[NG * (2*RNNK)];   // 1024 x 2560
__device__ float  g_bias[NG];
__device__ float  g_G  [8192 * NG];
__device__ uint2  g_WhhH[2 * 32 * 512];         // [dir][k4][gate]: 2x half2 (fp16 Whh)

// ---- helpers ----
__device__ __forceinline__ uint32_t s2u(const void* p) {
    uint32_t a;
    asm("{ .reg .u64 t; cvta.to.shared.u64 t, %1; cvt.u32.u64 %0, t; }" : "=r"(a) : "l"(p));
    return a;
}
__device__ __forceinline__ void split_h(float v, __half& h, __half& l) {
    h = __float2half_rn(v);
    l = __float2half_rn(v - __half2float(h));
}
__device__ __forceinline__ int coff(int c) {        // interleaved-32 column map (hi; lo = +32)
    return ((c >> 5) << 6) + (c & 31);
}
__device__ __forceinline__ uint32_t swz(uint32_t off) {
    return off ^ ((off >> 3) & 0x70);
}
__device__ __forceinline__ void cp16(uint32_t dst, const void* src) {
    asm volatile("cp.async.cg.shared.global [%0], [%1], 16;" :: "r"(dst), "l"(src));
}
__device__ __forceinline__ void ldm_x4(uint32_t* r, uint32_t addr) {
    asm volatile("ldmatrix.sync.aligned.m8n8.x4.shared.b16 {%0,%1,%2,%3}, [%4];"
                 : "=r"(r[0]), "=r"(r[1]), "=r"(r[2]), "=r"(r[3]) : "r"(addr));
}
__device__ __forceinline__ void mma16816(float* c, const uint32_t* a, const uint32_t* b) {
    asm volatile(
        "mma.sync.aligned.m16n8k16.row.col.f32.f16.f16.f32 "
        "{%0,%1,%2,%3}, {%4,%5,%6,%7}, {%8,%9}, {%0,%1,%2,%3};"
        : "+f"(c[0]), "+f"(c[1]), "+f"(c[2]), "+f"(c[3])
        : "r"(a[0]), "r"(a[1]), "r"(a[2]), "r"(a[3]), "r"(b[0]), "r"(b[1]));
}
__device__ __forceinline__ __half2 u2h2(uint32_t u) {
    __half2 h; asm("mov.b32 %0, %1;" : "=r"(*(uint32_t*)&h) : "r"(u)); return h;
}
// pack 8 halves into uint4
__device__ __forceinline__ uint4 pack8(const __half* v) {
    __half2 h2[4];
#pragma unroll
    for (int q = 0; q < 4; q++) h2[q] = __halves2half2(v[2*q], v[2*q+1]);
    return *(uint4*)h2;
}

// ---------------- prep kernels (vectorized: 8 elems/thread, uint4 stores) ----------------
__global__ void prep_A3(const float* __restrict__ x1w, const float* __restrict__ x1a0,
                        const float* __restrict__ x1a1, const float* __restrict__ x2w,
                        const float* __restrict__ x2a0, const float* __restrict__ x2a1) {
    int idx = blockIdx.x * 256 + threadIdx.x;
    if (idx >= MR * (KPADR / 8)) return;
    int r = idx / (KPADR / 8), c0 = (idx - r * (KPADR / 8)) * 8;
    int half = r >> 13, bl = r & 8191;
    __half hi[8], lo[8];
#pragma unroll
    for (int e = 0; e < 8; e++) {
        int c = c0 + e;
        float v = 0.f;
        if (c < 300)       v = (half ? x2w  : x1w )[(size_t)bl * EMB + c];
        else if (c < 556)  v = (half ? x2a0 : x1a0)[(size_t)bl * AH + (c - 300)];
        else if (c < 812)  v = (half ? x2a1 : x1a1)[(size_t)bl * AH + (c - 556)];
        split_h(v, hi[e], lo[e]);
    }
    __half* p = g_A3 + (size_t)r * (2 * KPADR) + ((c0 >> 5) << 6) + (c0 & 31);
    *(uint4*)p        = pack8(hi);
    *(uint4*)(p + 32) = pack8(lo);
}

__global__ void prep_W3(const float* __restrict__ Wattn, const float* __restrict__ vattn) {
    int idx = blockIdx.x * 256 + threadIdx.x;
    if (idx >= NR * (KPADR / 8)) return;
    int g = idx / (KPADR / 8), c0 = (idx - g * (KPADR / 8)) * 8;
    int i = g >> 8, a = g & 255;
    __half hi[8], lo[8];
#pragma unroll
    for (int e = 0; e < 8; e++) {
        int c = c0 + e;
        float v = (a < 250 && c < 812) ? Wattn[((size_t)(i * 250 + a)) * 812 + c] : 0.f;
        split_h(v, hi[e], lo[e]);
    }
    __half* p = g_W3 + (size_t)g * (2 * KPADR) + ((c0 >> 5) << 6) + (c0 & 31);
    *(uint4*)p        = pack8(hi);
    *(uint4*)(p + 32) = pack8(lo);
    if (idx < NR) {
        int i2 = idx >> 8, a2 = idx & 255;
        g_vbig[idx] = (a2 < 250) ? vattn[i2 * 250 + a2] : 0.f;
    }
}

__global__ void prep_Wih3(const float* __restrict__ Wf, const float* __restrict__ Wb,
                          const float* __restrict__ bf, const float* __restrict__ bb) {
    int idx = blockIdx.x * 256 + threadIdx.x;
    if (idx >= NG * (RNNK / 8)) return;
    int r = idx / (RNNK / 8), c0 = (idx - r * (RNNK / 8)) * 8;
    const float* src = (r < 512) ? Wf + (size_t)r * RNNK : Wb + (size_t)(r - 512) * RNNK;
    __half hi[8], lo[8];
#pragma unroll
    for (int e = 0; e < 8; e++) {
        split_h(src[c0 + e], hi[e], lo[e]);
    }
    __half* p = g_Wih3 + (size_t)r * (2 * RNNK) + ((c0 >> 5) << 6) + (c0 & 31);
    *(uint4*)p        = pack8(hi);
    *(uint4*)(p + 32) = pack8(lo);
    if (idx < NG) g_bias[idx] = (idx < 512) ? bf[idx] : bb[idx - 512];
}

__global__ void prep_headX13(const float* __restrict__ x1a0, const float* __restrict__ x1a1) {
    int idx = blockIdx.x * 256 + threadIdx.x;
    if (idx >= 8192 * 64) return;                   // 512 cols / 8
    int r = idx >> 6, c0 = (idx & 63) * 8;
    const float* src = (c0 < 256) ? x1a0 + (size_t)r * AH + c0
                                  : x1a1 + (size_t)r * AH + (c0 - 256);
    __half hi[8], lo[8];
#pragma unroll
    for (int e = 0; e < 8; e++) split_h(src[e], hi[e], lo[e]);
    __half* p = g_X13 + (size_t)r * (2 * RNNK) + ((c0 >> 5) << 6) + (c0 & 31);
    *(uint4*)p        = pack8(hi);
    *(uint4*)(p + 32) = pack8(lo);
}

// transpose x2_abstr_i [b][s][d] -> X2T3 rows (i*16+b)*256+d, cols s (interleaved-32)
__global__ void prep_X2T3(const float* __restrict__ a0, const float* __restrict__ a1,
                          const float* __restrict__ a2) {
    __shared__ float tile[32][33];
    int i = blockIdx.z >> 4, b = blockIdx.z & 15;
    int s0 = blockIdx.x * 32, d0 = blockIdx.y * 32;
    int tx = threadIdx.x, ty = threadIdx.y;
    const float* src = (i == 0) ? a0 : (i == 1) ? a1 : a2;
    tile[ty][tx] = src[((size_t)(b * 512 + s0 + ty)) * 256 + d0 + tx];
    __syncthreads();
    float v = tile[tx][ty];
    __half h, l; split_h(v, h, l);
    __half* p = g_X2T3 + ((size_t)((i * 16 + b) * 256 + d0 + ty)) * 1024 + s0 * 2 + tx;
    p[0] = h; p[32] = l;
}

// fp16 Whh, layout [dir][k4 0..31][gate 0..511]
__global__ void prep_WhhH(const float* __restrict__ Whhf, const float* __restrict__ Whhb) {
    int idx = blockIdx.x * 256 + threadIdx.x;
    if (idx >= 2 * 32 * 512) return;
    int d = idx >> 14, k4 = (idx >> 9) & 31, g = idx & 511;
    const float* s = d ? Whhb : Whhf;
    size_t base = (size_t)g * HH + k4 * 4;
    __half2 p0 = __floats2half2_rn(s[base],     s[base + 1]);
    __half2 p1 = __floats2half2_rn(s[base + 2], s[base + 3]);
    uint2 u;
    u.x = *(uint32_t*)&p0;
    u.y = *(uint32_t*)&p1;
    g_WhhH[idx] = u;
}

// ---------------- HMMA GEMM: grid-per-tile, split fp16, interleaved-32 storage --------
// Chunk = 32 base cols = one 128B smem row slice (hi|lo). Stage 32KB, 3 stages, 2 CTA/SM.
// NPASS=3: Ah*Bh + Al*Bh + Ah*Bl (exact).  NPASS=2: drops Ah*Bl.
// EPI: 0 scores f32 | 1 R split-out relu(+v) | 2 gin f32+bias | 3 X13 split-out
#define HG_STAGE 32768
#define HG_SMEM  (3 * HG_STAGE)

template <int EPI, int NPASS>
__global__ void __launch_bounds__(256, 2)
hgemm(const __half* __restrict__ A, const __half* __restrict__ B,
      float* __restrict__ Cf, __half* __restrict__ Cb,
      int ldA, int ldB, int ldC, int nkc,
      int zdiv, long sAb, long sAi, long sBb, long sBi, long sCb, long sCi,
      const float* __restrict__ evec, int rowSplit) {
    extern __shared__ __align__(1024) char smem[];
    const uint32_t su = s2u(smem);
    const int tid = threadIdx.x, lane = tid & 31, wid = tid >> 5;

    const int z = blockIdx.z, zi = z % zdiv, zb = z / zdiv;
    A += zb * sAb + zi * sAi;
    B += zb * sBb + zi * sBi;
    if (EPI == 0 || EPI == 2) Cf += zb * sCb + zi * sCi;
    if (EPI == 3)             Cb += zb * sCb + zi * sCi;
    const int m0 = blockIdx.y * 128, n0 = blockIdx.x * 128;
    const int r0 = tid >> 3, c16 = tid & 7;

    float acc[2][8][4];
#pragma unroll
    for (int i = 0; i < 2; i++)
#pragma unroll
        for (int j = 0; j < 8; j++)
#pragma unroll
            for (int q = 0; q < 4; q++) acc[i][j][q] = 0.f;

    const int wm = wid & 3, wn = wid >> 2;
    const int a_row = wm * 32 + (lane & 15);
    const int a_kb  = (lane >> 4) * 8;           // halves
    const int b_row = wn * 64 + ((lane >> 4) << 3) + (lane & 7);
    const int b_kb  = ((lane >> 3) & 1) * 8;     // halves

    // issue chunk kc (32 base cols = 64 storage halves = 128B row) into stage st
    auto issue = [&](int kc, int st) {
        const __half* Ag = A + (size_t)(m0 + r0) * ldA + kc * 64 + c16 * 8;
        const __half* Bg = B + (size_t)(n0 + r0) * ldB + kc * 64 + c16 * 8;
        uint32_t sb = su + st * HG_STAGE;
#pragma unroll
        for (int j = 0; j < 4; ++j) {
            uint32_t off = swz((r0 + 32 * j) * 128 + c16 * 16);
            cp16(sb + off,          Ag + (size_t)(32 * j) * ldA);
            cp16(sb + 16384 + off,  Bg + (size_t)(32 * j) * ldB);
        }
        asm volatile("cp.async.commit_group;" ::: "memory");
    };

    issue(0, 0);
    issue(1, 1);
    for (int kc = 0; kc < nkc; ++kc) {
        const int st = kc % 3;
        if (kc == nkc - 1)
            asm volatile("cp.async.wait_group 0;" ::: "memory");  // last chunk IS the newest group
        else
            asm volatile("cp.async.wait_group 1;" ::: "memory");
        __syncthreads();
        if (kc + 2 < nkc) issue(kc + 2, (kc + 2) % 3);
        const uint32_t sA = su + st * HG_STAGE;
        const uint32_t sB = sA + 16384;
#pragma unroll
        for (int s = 0; s < 2; ++s) {
            const uint32_t aH0 = (uint32_t)(a_row)      * 128 + (s * 16 + a_kb) * 2;
            const uint32_t aH1 = (uint32_t)(a_row + 16) * 128 + (s * 16 + a_kb) * 2;
            uint32_t ah[2][4], al[2][4], bb[4][4];
            ldm_x4(ah[0], sA + swz(aH0));
            ldm_x4(ah[1], sA + swz(aH1));
#pragma unroll
            for (int nj = 0; nj < 4; ++nj) {
                uint32_t off = (uint32_t)(b_row + nj * 16) * 128 + (s * 16 + b_kb) * 2;
                ldm_x4(bb[nj], sB + swz(off));
            }
            // pass 1: Ah * Bh
#pragma unroll
            for (int mi = 0; mi < 2; ++mi)
#pragma unroll
                for (int ni = 0; ni < 8; ++ni)
                    mma16816(acc[mi][ni], ah[mi], &bb[ni >> 1][(ni & 1) * 2]);
            // pass 2: Al * Bh
            ldm_x4(al[0], sA + swz(aH0 + 64));
            ldm_x4(al[1], sA + swz(aH1 + 64));
#pragma unroll
            for (int mi = 0; mi < 2; ++mi)
#pragma unroll
                for (int ni = 0; ni < 8; ++ni)
                    mma16816(acc[mi][ni], al[mi], &bb[ni >> 1][(ni & 1) * 2]);
            // pass 3: Ah * Bl (reuse bb regs) — exact mode only
            if (NPASS == 3) {
#pragma unroll
                for (int nj = 0; nj < 4; ++nj) {
                    uint32_t off = (uint32_t)(b_row + nj * 16) * 128 + (s * 16 + b_kb) * 2 + 64;
                    ldm_x4(bb[nj], sB + swz(off));
                }
#pragma unroll
                for (int mi = 0; mi < 2; ++mi)
#pragma unroll
                    for (int ni = 0; ni < 8; ++ni)
                        mma16816(acc[mi][ni], ah[mi], &bb[ni >> 1][(ni & 1) * 2]);
            }
        }
    }

    const int tq = lane >> 2, tr = (lane & 3) * 2;
#pragma unroll
    for (int mi = 0; mi < 2; ++mi) {
#pragma unroll
        for (int h = 0; h < 2; ++h) {
            const int mg = m0 + wm * 32 + mi * 16 + h * 8 + tq;
#pragma unroll
            for (int ni = 0; ni < 8; ++ni) {
                const int nc = n0 + wn * 64 + ni * 8 + tr;
                float v0 = acc[mi][ni][h * 2], v1 = acc[mi][ni][h * 2 + 1];
                if (EPI == 0) {
                    *(float2*)(Cf + (size_t)mg * ldC + nc) = make_float2(v0, v1);
                } else if (EPI == 2) {
                    *(float2*)(Cf + (size_t)mg * ldC + nc) =
                        make_float2(v0 + evec[nc], v1 + evec[nc + 1]);
                } else if (EPI == 1) {
                    const bool isB = (mg >= rowSplit);
                    v0 = fmaxf(v0, 0.f); v1 = fmaxf(v1, 0.f);
                    if (isB) { v0 *= evec[nc]; v1 *= evec[nc + 1]; }
                    __half h0, l0, h1, l1;
                    split_h(v0, h0, l0); split_h(v1, h1, l1);
                    __half* p = (isB ? g_R3B + (size_t)(mg - rowSplit) * (2 * NR)
                                     : g_R3A + (size_t)mg * (2 * NR)) + coff(nc);
                    *(__half2*)(p)      = __halves2half2(h0, h1);
                    *(__half2*)(p + 32) = __halves2half2(l0, l1);
                } else {  // EPI == 3
                    __half h0, l0, h1, l1;
                    split_h(v0, h0, l0); split_h(v1, h1, l1);
                    __half* p = Cb + (size_t)mg * (2 * RNNK) + coff(nc);
                    *(__half2*)(p)      = __halves2half2(h0, h1);
                    *(__half2*)(p + 32) = __halves2half2(l0, l1);
                }
            }
        }
    }
}

// ---------------- softmax: rows of 512 -> split fp16 alpha (interleaved-32) ----------------
__global__ void softmax_kernel(const float* __restrict__ S, const unsigned char* __restrict__ x2mask) {
    const float NEGF = -3.4e38f;
    const float2* row = (const float2*)(S + (size_t)blockIdx.x * 512);
    int b = blockIdx.x / 1536;
    const unsigned char* mk = x2mask + b * 512;
    int t = threadIdx.x;
    float2 v = row[t];
    if (mk[2 * t])     v.x = NEGF;
    if (mk[2 * t + 1]) v.y = NEGF;
    __shared__ float red[8];
    float mx = fmaxf(v.x, v.y);
#pragma unroll
    for (int o = 16; o; o >>= 1) mx = fmaxf(mx, __shfl_xor_sync(0xffffffffu, mx, o));
    if ((t & 31) == 0) red[t >> 5] = mx;
    __syncthreads();
    float M = red[0];
#pragma unroll
    for (int i = 1; i < 8; i++) M = fmaxf(M, red[i]);
    __syncthreads();
    float e0 = __expf(v.x - M), e1 = __expf(v.y - M);
    float s = e0 + e1;
#pragma unroll
    for (int o = 16; o; o >>= 1) s += __shfl_xor_sync(0xffffffffu, s, o);
    if ((t & 31) == 0) red[t >> 5] = s;
    __syncthreads();
    float tot = red[0];
#pragma unroll
    for (int i = 1; i < 8; i++) tot += red[i];
    float inv = __fdividef(1.f, tot);
    float p0 = e0 * inv, p1 = e1 * inv;
    __half h0, l0, h1, l1;
    split_h(p0, h0, l0); split_h(p1, h1, l1);
    __half* p = g_AL3 + (size_t)blockIdx.x * 1024 + coff(2 * t);
    *(__half2*)(p)      = __halves2half2(h0, h1);
    *(__half2*)(p + 32) = __halves2half2(l0, l1);
}

// ---------------- BiLSTM (R12 version): fp16 Whh, HFMA2 partial sums, zbuf publish ----------
__device__ __forceinline__ float sigf(float x) { return __fdividef(1.f, 1.f + __expf(-x)); }
__device__ __forceinline__ float tanhf_fast(float x) { return 1.f - __fdividef(2.f, __expf(2.f * x) + 1.f); }

#define LSTM_SMEM (16 * 512 * 8 + 512 * 4 + 256)

__global__ void __launch_bounds__(512, 1)
lstm_kernel(const float* __restrict__ G, float* __restrict__ out) {
    extern __shared__ char smraw[];
    uint2* Ws   = (uint2*)smraw;                       // [k4 0..15][512]
    float* zbuf = (float*)(smraw + 16 * 512 * 8);
    __half* hsH = (__half*)(smraw + 16 * 512 * 8 + 512 * 4);

    const int dir = blockIdx.x & 1;
    const int b   = blockIdx.x >> 1;
    const int g   = threadIdx.x;

    const uint2* Wg = g_WhhH + (size_t)dir * 32 * 512;
    for (int i = g; i < 16 * 512; i += 512) Ws[i] = Wg[i];
    uint2 wr[16];
#pragma unroll
    for (int j = 0; j < 16; j++) wr[j] = Wg[(16 + j) * 512 + g];
    if (g < 128) hsH[g] = __float2half(0.f);
    float c = 0.f;
    __syncthreads();

    const float* gptr = G + (size_t)b * 512 * NG + dir * 512 + g;
    int trow = dir ? 511 : 0;
    const int tstep = dir ? -1 : 1;
    float gv = gptr[(size_t)trow * NG];

    const __half2 z2 = __floats2half2_rn(0.f, 0.f);

    for (int t = 0; t < 512; ++t) {
        float gcur = gv;
        if (t + 1 < 512) gv = gptr[(size_t)(trow + tstep) * NG];

        uint4 hu[16];
        const uint4* hp = (const uint4*)hsH;
#pragma unroll
        for (int j = 0; j < 16; j++) hu[j] = hp[j];

        __half2 accA[4] = {z2, z2, z2, z2};
        __half2 accB[4] = {z2, z2, z2, z2};
#pragma unroll
        for (int k4 = 0; k4 < 16; k4++) {
            uint2 w = Ws[k4 * 512 + g];
            uint4 h4 = hu[k4 >> 1];
            uint32_t ha = (k4 & 1) ? h4.z : h4.x;
            uint32_t hb = (k4 & 1) ? h4.w : h4.y;
            accA[k4 & 3] = __hfma2(u2h2(w.x), u2h2(ha), accA[k4 & 3]);
            accB[k4 & 3] = __hfma2(u2h2(w.y), u2h2(hb), accB[k4 & 3]);
        }
#pragma unroll
        for (int j = 0; j < 16; j++) {
            int k4 = 16 + j;
            uint2 w = wr[j];
            uint4 h4 = hu[k4 >> 1];
            uint32_t ha = (k4 & 1) ? h4.z : h4.x;
            uint32_t hb = (k4 & 1) ? h4.w : h4.y;
            accA[j & 3] = __hfma2(u2h2(w.x), u2h2(ha), accA[j & 3]);
            accB[j & 3] = __hfma2(u2h2(w.y), u2h2(hb), accB[j & 3]);
        }
        float zsum = 0.f;
#pragma unroll
        for (int j = 0; j < 4; j++) {
            float2 fa = __half22float2(accA[j]);
            float2 fb = __half22float2(accB[j]);
            zsum += (fa.x + fa.y) + (fb.x + fb.y);
        }
        zbuf[g] = zsum + gcur;
        __syncthreads();

        if (g < 128) {
            float zi = zbuf[g], zf = zbuf[g + 128], zg = zbuf[g + 256], zo = zbuf[g + 384];
            c = sigf(zf) * c + sigf(zi) * tanhf_fast(zg);
            float h = sigf(zo) * tanhf_fast(c);
            hsH[g] = __float2half_rn(h);
            out[((size_t)b * 512 + trow) * 256 + dir * 128 + g] = h;
        }
        __syncthreads();
        trow += tstep;
    }
}

// ---------------- launch ----------------
extern "C" void kernel_launch(void* const* d_in, const int* in_sizes, int n_in,
                              void* d_out, int out_size) {
    const float* x1w  = (const float*)d_in[0];
    const float* x1a0 = (const float*)d_in[1];
    const float* x1a1 = (const float*)d_in[2];
    const float* x2w  = (const float*)d_in[3];
    const float* x2a0 = (const float*)d_in[4];
    const float* x2a1 = (const float*)d_in[5];
    const float* x2a2 = (const float*)d_in[6];
    const unsigned char* x2mask = (const unsigned char*)d_in[8];
    const float* Wattn = (const float*)d_in[9];
    const float* vattn = (const float*)d_in[10];
    const float* Wihf = (const float*)d_in[11];
    const float* Whhf = (const float*)d_in[12];
    const float* bf   = (const float*)d_in[13];
    const float* Wihb = (const float*)d_in[14];
    const float* Whhb = (const float*)d_in[15];
    const float* bb   = (const float*)d_in[16];
    float* out = (float*)d_out;

    static bool attr_done = false;
    if (!attr_done) {
        cudaFuncSetAttribute(lstm_kernel, cudaFuncAttributeMaxDynamicSharedMemorySize, LSTM_SMEM);
        cudaFuncSetAttribute((const void*)hgemm<0,3>, cudaFuncAttributeMaxDynamicSharedMemorySize, HG_SMEM);
        cudaFuncSetAttribute((const void*)hgemm<1,3>, cudaFuncAttributeMaxDynamicSharedMemorySize, HG_SMEM);
        cudaFuncSetAttribute((const void*)hgemm<2,2>, cudaFuncAttributeMaxDynamicSharedMemorySize, HG_SMEM);
        cudaFuncSetAttribute((const void*)hgemm<3,2>, cudaFuncAttributeMaxDynamicSharedMemorySize, HG_SMEM);
        attr_done = true;
    }

    __half *A3, *W3, *R3A, *R3B, *AL3, *X2T3, *X13, *Wih3;
    float *vbig, *S, *bias, *Gm;
    cudaGetSymbolAddress((void**)&A3,   g_A3);
    cudaGetSymbolAddress((void**)&W3,   g_W3);
    cudaGetSymbolAddress((void**)&vbig, g_vbig);
    cudaGetSymbolAddress((void**)&R3A,  g_R3A);
    cudaGetSymbolAddress((void**)&R3B,  g_R3B);
    cudaGetSymbolAddress((void**)&S,    g_S);
    cudaGetSymbolAddress((void**)&AL3,  g_AL3);
    cudaGetSymbolAddress((void**)&X2T3, g_X2T3);
    cudaGetSymbolAddress((void**)&X13,  g_X13);
    cudaGetSymbolAddress((void**)&Wih3, g_Wih3);
    cudaGetSymbolAddress((void**)&bias, g_bias);
    cudaGetSymbolAddress((void**)&Gm,   g_G);

    // launches 0..2, then the R GEMM at index 3 (ncu profiles launch 3)
    prep_A3  <<<(MR * (KPADR / 8) + 255) / 256, 256>>>(x1w, x1a0, x1a1, x2w, x2a0, x2a1);
    prep_W3  <<<(NR * (KPADR / 8) + 255) / 256, 256>>>(Wattn, vattn);
    prep_WhhH<<<(2 * 32 * 512 + 255) / 256, 256>>>(Whhf, Whhb);

    // R = relu(A3 * W3^T) (+v for x2 rows): M=16384, N=768, baseK=832 -> 26 chunks, 3-pass
    {
        dim3 grid(6, 128, 1);
        hgemm<1,3><<<grid, 256, HG_SMEM>>>(A3, W3, nullptr, nullptr,
            2 * KPADR, 2 * KPADR, 0, 26,
            1, 0, 0, 0, 0, 0, 0, vbig, 8192);
    }

    prep_Wih3   <<<(NG * (RNNK / 8) + 255) / 256, 256>>>(Wihf, Wihb, bf, bb);
    prep_headX13<<<(8192 * 64 + 255) / 256, 256>>>(x1a0, x1a1);
    {
        dim3 grid(16, 8, 48), blk(32, 32, 1);
        prep_X2T3<<<grid, blk>>>(x2a0, x2a1, x2a2);
    }

    // scores per (b,i): S = r1 * r2^T: M=512, N=512, baseK=256 -> 8 chunks, 3-pass
    {
        dim3 grid(4, 4, 48);
        hgemm<0,3><<<grid, 256, HG_SMEM>>>(R3A, R3B, S, nullptr,
            2 * NR, 2 * NR, 512, 8,
            3,
            (long)512 * 2 * NR, 512, (long)512 * 2 * NR, 512,
            (long)3 * 512 * 512, (long)512 * 512, nullptr, 0);
    }
    softmax_kernel<<<48 * 512, 256>>>(S, x2mask);
    // attn per (b,i): X13[:, base 512 + i*256 ..] = alpha * x2_i^T: M=512, N=256, baseK=512 -> 16 chunks, 2-pass
    {
        dim3 grid(2, 4, 48);
        hgemm<3,2><<<grid, 256, HG_SMEM>>>(AL3, X2T3, nullptr, X13 + 1024,
            1024, 1024, 0, 16,
            3,
            (long)3 * 512 * 1024, (long)512 * 1024,
            (long)256 * 1024, (long)16 * 256 * 1024,
            (long)512 * 2 * RNNK, 512, nullptr, 0);
    }
    // g_in = X13 * Wih3^T + bias: M=8192, N=1024, baseK=1280 -> 40 chunks, 2-pass
    {
        dim3 grid(8, 64, 1);
        hgemm<2,2><<<grid, 256, HG_SMEM>>>(X13, Wih3, Gm, nullptr,
            2 * RNNK, 2 * RNNK, NG, 40,
            1, 0, 0, 0, 0, 0, 0, bias, 0);
    }
    lstm_kernel<<<32, 512, LSTM_SMEM>>>(Gm, out);
}

// round 16
// speedup vs baseline: 1.1080x; 1.0540x over previous
#include <cuda_runtime.h>
#include <cuda_fp16.h>
#include <cstdint>

typedef unsigned long long ull;

#define Bz   16
#define EMB  300
#define AH   256
#define KPADR 832              // padded 812 -> 832 (26*32)
#define NR   768               // 3*256
#define MR   16384
#define RNNK 1280
#define NG   1024
#define HH   128

// ---- scratch: split fp16, INTERLEAVED-32 storage: [hi(0:32)|lo(0:32)|hi(32:64)|lo...] ----
__device__ __align__(16) __half g_A3 [MR * (2*KPADR)];   // 16384 x 1664
__device__ __align__(16) __half g_W3 [NR * (2*KPADR)];   // 768 x 1664
__device__ float  g_vbig[NR];
__device__ __align__(16) __half g_R3A[8192 * (2*NR)];    // x1 rows: 8192 x 1536
__device__ __align__(16) __half g_R3B[8192 * (2*NR)];    // x2 rows (v-scaled)
__device__ float  g_S  [48 * 512 * 512];
__device__ __align__(16) __half g_AL3[48 * 512 * 1024];  // alpha, rows (b*3+i)*512+l
__device__ __align__(16) __half g_X2T3[48 * 256 * 1024]; // x2^T, rows (i*16+b)*256+d
__device__ __align__(16) __half g_X13[8192 * (2*RNNK)];  // X1CAT, 8192 x 2560
__device__ __align__(16) __half g_Wih3[NG * (2*RNNK)];   // 1024 x 2560
__device__ float  g_bias[NG];
__device__ float  g_G  [8192 * NG];
__device__ uint2  g_WhhH[2 * 32 * 512];         // [dir][k4][gate]: 2x half2 (fp16 Whh)

// ---- helpers ----
__device__ __forceinline__ uint32_t s2u(const void* p) {
    uint32_t a;
    asm("{ .reg .u64 t; cvta.to.shared.u64 t, %1; cvt.u32.u64 %0, t; }" : "=r"(a) : "l"(p));
    return a;
}
__device__ __forceinline__ void split_h(float v, __half& h, __half& l) {
    h = __float2half_rn(v);
    l = __float2half_rn(v - __half2float(h));
}
__device__ __forceinline__ int coff(int c) {        // interleaved-32 column map (hi; lo = +32)
    return ((c >> 5) << 6) + (c & 31);
}
__device__ __forceinline__ uint32_t swz(uint32_t off) {
    return off ^ ((off >> 3) & 0x70);
}
__device__ __forceinline__ void cp16(uint32_t dst, const void* src) {
    asm volatile("cp.async.cg.shared.global [%0], [%1], 16;" :: "r"(dst), "l"(src));
}
__device__ __forceinline__ void ldm_x4(uint32_t* r, uint32_t addr) {
    asm volatile("ldmatrix.sync.aligned.m8n8.x4.shared.b16 {%0,%1,%2,%3}, [%4];"
                 : "=r"(r[0]), "=r"(r[1]), "=r"(r[2]), "=r"(r[3]) : "r"(addr));
}
__device__ __forceinline__ void mma16816(float* c, const uint32_t* a, const uint32_t* b) {
    asm volatile(
        "mma.sync.aligned.m16n8k16.row.col.f32.f16.f16.f32 "
        "{%0,%1,%2,%3}, {%4,%5,%6,%7}, {%8,%9}, {%0,%1,%2,%3};"
        : "+f"(c[0]), "+f"(c[1]), "+f"(c[2]), "+f"(c[3])
        : "r"(a[0]), "r"(a[1]), "r"(a[2]), "r"(a[3]), "r"(b[0]), "r"(b[1]));
}
__device__ __forceinline__ __half2 u2h2(uint32_t u) {
    __half2 h; asm("mov.b32 %0, %1;" : "=r"(*(uint32_t*)&h) : "r"(u)); return h;
}
__device__ __forceinline__ uint4 pack8(const __half* v) {
    __half2 h2[4];
#pragma unroll
    for (int q = 0; q < 4; q++) h2[q] = __halves2half2(v[2*q], v[2*q+1]);
    return *(uint4*)h2;
}

// ---------------- prep kernels (vectorized: 8 elems/thread, uint4 stores) ----------------
__global__ void prep_A3(const float* __restrict__ x1w, const float* __restrict__ x1a0,
                        const float* __restrict__ x1a1, const float* __restrict__ x2w,
                        const float* __restrict__ x2a0, const float* __restrict__ x2a1) {
    int idx = blockIdx.x * 256 + threadIdx.x;
    if (idx >= MR * (KPADR / 8)) return;
    int r = idx / (KPADR / 8), c0 = (idx - r * (KPADR / 8)) * 8;
    int half = r >> 13, bl = r & 8191;
    __half hi[8], lo[8];
#pragma unroll
    for (int e = 0; e < 8; e++) {
        int c = c0 + e;
        float v = 0.f;
        if (c < 300)       v = (half ? x2w  : x1w )[(size_t)bl * EMB + c];
        else if (c < 556)  v = (half ? x2a0 : x1a0)[(size_t)bl * AH + (c - 300)];
        else if (c < 812)  v = (half ? x2a1 : x1a1)[(size_t)bl * AH + (c - 556)];
        split_h(v, hi[e], lo[e]);
    }
    __half* p = g_A3 + (size_t)r * (2 * KPADR) + ((c0 >> 5) << 6) + (c0 & 31);
    *(uint4*)p        = pack8(hi);
    *(uint4*)(p + 32) = pack8(lo);
}

__global__ void prep_W3(const float* __restrict__ Wattn, const float* __restrict__ vattn) {
    int idx = blockIdx.x * 256 + threadIdx.x;
    if (idx >= NR * (KPADR / 8)) return;
    int g = idx / (KPADR / 8), c0 = (idx - g * (KPADR / 8)) * 8;
    int i = g >> 8, a = g & 255;
    __half hi[8], lo[8];
#pragma unroll
    for (int e = 0; e < 8; e++) {
        int c = c0 + e;
        float v = (a < 250 && c < 812) ? Wattn[((size_t)(i * 250 + a)) * 812 + c] : 0.f;
        split_h(v, hi[e], lo[e]);
    }
    __half* p = g_W3 + (size_t)g * (2 * KPADR) + ((c0 >> 5) << 6) + (c0 & 31);
    *(uint4*)p        = pack8(hi);
    *(uint4*)(p + 32) = pack8(lo);
    if (idx < NR) {
        int i2 = idx >> 8, a2 = idx & 255;
        g_vbig[idx] = (a2 < 250) ? vattn[i2 * 250 + a2] : 0.f;
    }
}

__global__ void prep_Wih3(const float* __restrict__ Wf, const float* __restrict__ Wb,
                          const float* __restrict__ bf, const float* __restrict__ bb) {
    int idx = blockIdx.x * 256 + threadIdx.x;
    if (idx >= NG * (RNNK / 8)) return;
    int r = idx / (RNNK / 8), c0 = (idx - r * (RNNK / 8)) * 8;
    const float* src = (r < 512) ? Wf + (size_t)r * RNNK : Wb + (size_t)(r - 512) * RNNK;
    __half hi[8], lo[8];
#pragma unroll
    for (int e = 0; e < 8; e++) {
        split_h(src[c0 + e], hi[e], lo[e]);
    }
    __half* p = g_Wih3 + (size_t)r * (2 * RNNK) + ((c0 >> 5) << 6) + (c0 & 31);
    *(uint4*)p        = pack8(hi);
    *(uint4*)(p + 32) = pack8(lo);
    if (idx < NG) g_bias[idx] = (idx < 512) ? bf[idx] : bb[idx - 512];
}

__global__ void prep_headX13(const float* __restrict__ x1a0, const float* __restrict__ x1a1) {
    int idx = blockIdx.x * 256 + threadIdx.x;
    if (idx >= 8192 * 64) return;                   // 512 cols / 8
    int r = idx >> 6, c0 = (idx & 63) * 8;
    const float* src = (c0 < 256) ? x1a0 + (size_t)r * AH + c0
                                  : x1a1 + (size_t)r * AH + (c0 - 256);
    __half hi[8], lo[8];
#pragma unroll
    for (int e = 0; e < 8; e++) split_h(src[e], hi[e], lo[e]);
    __half* p = g_X13 + (size_t)r * (2 * RNNK) + ((c0 >> 5) << 6) + (c0 & 31);
    *(uint4*)p        = pack8(hi);
    *(uint4*)(p + 32) = pack8(lo);
}

// transpose x2_abstr_i [b][s][d] -> X2T3 rows (i*16+b)*256+d, cols s (interleaved-32)
__global__ void prep_X2T3(const float* __restrict__ a0, const float* __restrict__ a1,
                          const float* __restrict__ a2) {
    __shared__ float tile[32][33];
    int i = blockIdx.z >> 4, b = blockIdx.z & 15;
    int s0 = blockIdx.x * 32, d0 = blockIdx.y * 32;
    int tx = threadIdx.x, ty = threadIdx.y;
    const float* src = (i == 0) ? a0 : (i == 1) ? a1 : a2;
    tile[ty][tx] = src[((size_t)(b * 512 + s0 + ty)) * 256 + d0 + tx];
    __syncthreads();
    float v = tile[tx][ty];
    __half h, l; split_h(v, h, l);
    __half* p = g_X2T3 + ((size_t)((i * 16 + b) * 256 + d0 + ty)) * 1024 + s0 * 2 + tx;
    p[0] = h; p[32] = l;
}

// fp16 Whh, layout [dir][k4 0..31][gate 0..511]
__global__ void prep_WhhH(const float* __restrict__ Whhf, const float* __restrict__ Whhb) {
    int idx = blockIdx.x * 256 + threadIdx.x;
    if (idx >= 2 * 32 * 512) return;
    int d = idx >> 14, k4 = (idx >> 9) & 31, g = idx & 511;
    const float* s = d ? Whhb : Whhf;
    size_t base = (size_t)g * HH + k4 * 4;
    __half2 p0 = __floats2half2_rn(s[base],     s[base + 1]);
    __half2 p1 = __floats2half2_rn(s[base + 2], s[base + 3]);
    uint2 u;
    u.x = *(uint32_t*)&p0;
    u.y = *(uint32_t*)&p1;
    g_WhhH[idx] = u;
}

// ---------------- HMMA GEMM: grid-per-tile, split fp16, interleaved-32 storage --------
// Chunk = 32 base cols = one 128B smem row slice (hi|lo). Stage 32KB, 3 stages, 2 CTA/SM.
// NPASS=3: Ah*Bh + Al*Bh + Ah*Bl (exact).  NPASS=2: drops Ah*Bl.
// EPI: 0 scores f32 | 1 R split-out relu(+v) | 2 gin f32+bias | 3 X13 split-out
#define HG_STAGE 32768
#define HG_SMEM  (3 * HG_STAGE)

template <int EPI, int NPASS>
__global__ void __launch_bounds__(256, 2)
hgemm(const __half* __restrict__ A, const __half* __restrict__ B,
      float* __restrict__ Cf, __half* __restrict__ Cb,
      int ldA, int ldB, int ldC, int nkc,
      int zdiv, long sAb, long sAi, long sBb, long sBi, long sCb, long sCi,
      const float* __restrict__ evec, int rowSplit) {
    extern __shared__ __align__(1024) char smem[];
    const uint32_t su = s2u(smem);
    const int tid = threadIdx.x, lane = tid & 31, wid = tid >> 5;

    const int z = blockIdx.z, zi = z % zdiv, zb = z / zdiv;
    A += zb * sAb + zi * sAi;
    B += zb * sBb + zi * sBi;
    if (EPI == 0 || EPI == 2) Cf += zb * sCb + zi * sCi;
    if (EPI == 3)             Cb += zb * sCb + zi * sCi;
    const int m0 = blockIdx.y * 128, n0 = blockIdx.x * 128;
    const int r0 = tid >> 3, c16 = tid & 7;

    float acc[2][8][4];
#pragma unroll
    for (int i = 0; i < 2; i++)
#pragma unroll
        for (int j = 0; j < 8; j++)
#pragma unroll
            for (int q = 0; q < 4; q++) acc[i][j][q] = 0.f;

    const int wm = wid & 3, wn = wid >> 2;
    const int a_row = wm * 32 + (lane & 15);
    const int a_kb  = (lane >> 4) * 8;           // halves
    const int b_row = wn * 64 + ((lane >> 4) << 3) + (lane & 7);
    const int b_kb  = ((lane >> 3) & 1) * 8;     // halves

    auto issue = [&](int kc, int st) {
        const __half* Ag = A + (size_t)(m0 + r0) * ldA + kc * 64 + c16 * 8;
        const __half* Bg = B + (size_t)(n0 + r0) * ldB + kc * 64 + c16 * 8;
        uint32_t sb = su + st * HG_STAGE;
#pragma unroll
        for (int j = 0; j < 4; ++j) {
            uint32_t off = swz((r0 + 32 * j) * 128 + c16 * 16);
            cp16(sb + off,          Ag + (size_t)(32 * j) * ldA);
            cp16(sb + 16384 + off,  Bg + (size_t)(32 * j) * ldB);
        }
        asm volatile("cp.async.commit_group;" ::: "memory");
    };

    issue(0, 0);
    issue(1, 1);
    for (int kc = 0; kc < nkc; ++kc) {
        const int st = kc % 3;
        if (kc == nkc - 1)
            asm volatile("cp.async.wait_group 0;" ::: "memory");  // last chunk IS the newest group
        else
            asm volatile("cp.async.wait_group 1;" ::: "memory");
        __syncthreads();
        if (kc + 2 < nkc) issue(kc + 2, (kc + 2) % 3);
        const uint32_t sA = su + st * HG_STAGE;
        const uint32_t sB = sA + 16384;
#pragma unroll
        for (int s = 0; s < 2; ++s) {
            const uint32_t aH0 = (uint32_t)(a_row)      * 128 + (s * 16 + a_kb) * 2;
            const uint32_t aH1 = (uint32_t)(a_row + 16) * 128 + (s * 16 + a_kb) * 2;
            uint32_t ah[2][4], al[2][4], bb[4][4];
            ldm_x4(ah[0], sA + swz(aH0));
            ldm_x4(ah[1], sA + swz(aH1));
#pragma unroll
            for (int nj = 0; nj < 4; ++nj) {
                uint32_t off = (uint32_t)(b_row + nj * 16) * 128 + (s * 16 + b_kb) * 2;
                ldm_x4(bb[nj], sB + swz(off));
            }
            // pass 1: Ah * Bh
#pragma unroll
            for (int mi = 0; mi < 2; ++mi)
#pragma unroll
                for (int ni = 0; ni < 8; ++ni)
                    mma16816(acc[mi][ni], ah[mi], &bb[ni >> 1][(ni & 1) * 2]);
            // pass 2: Al * Bh
            ldm_x4(al[0], sA + swz(aH0 + 64));
            ldm_x4(al[1], sA + swz(aH1 + 64));
#pragma unroll
            for (int mi = 0; mi < 2; ++mi)
#pragma unroll
                for (int ni = 0; ni < 8; ++ni)
                    mma16816(acc[mi][ni], al[mi], &bb[ni >> 1][(ni & 1) * 2]);
            // pass 3: Ah * Bl (reuse bb regs) — exact mode only
            if (NPASS == 3) {
#pragma unroll
                for (int nj = 0; nj < 4; ++nj) {
                    uint32_t off = (uint32_t)(b_row + nj * 16) * 128 + (s * 16 + b_kb) * 2 + 64;
                    ldm_x4(bb[nj], sB + swz(off));
                }
#pragma unroll
                for (int mi = 0; mi < 2; ++mi)
#pragma unroll
                    for (int ni = 0; ni < 8; ++ni)
                        mma16816(acc[mi][ni], ah[mi], &bb[ni >> 1][(ni & 1) * 2]);
            }
        }
    }

    const int tq = lane >> 2, tr = (lane & 3) * 2;
#pragma unroll
    for (int mi = 0; mi < 2; ++mi) {
#pragma unroll
        for (int h = 0; h < 2; ++h) {
            const int mg = m0 + wm * 32 + mi * 16 + h * 8 + tq;
#pragma unroll
            for (int ni = 0; ni < 8; ++ni) {
                const int nc = n0 + wn * 64 + ni * 8 + tr;
                float v0 = acc[mi][ni][h * 2], v1 = acc[mi][ni][h * 2 + 1];
                if (EPI == 0) {
                    *(float2*)(Cf + (size_t)mg * ldC + nc) = make_float2(v0, v1);
                } else if (EPI == 2) {
                    *(float2*)(Cf + (size_t)mg * ldC + nc) =
                        make_float2(v0 + evec[nc], v1 + evec[nc + 1]);
                } else if (EPI == 1) {
                    const bool isB = (mg >= rowSplit);
                    v0 = fmaxf(v0, 0.f); v1 = fmaxf(v1, 0.f);
                    if (isB) { v0 *= evec[nc]; v1 *= evec[nc + 1]; }
                    __half h0, l0, h1, l1;
                    split_h(v0, h0, l0); split_h(v1, h1, l1);
                    __half* p = (isB ? g_R3B + (size_t)(mg - rowSplit) * (2 * NR)
                                     : g_R3A + (size_t)mg * (2 * NR)) + coff(nc);
                    *(__half2*)(p)      = __halves2half2(h0, h1);
                    *(__half2*)(p + 32) = __halves2half2(l0, l1);
                } else {  // EPI == 3
                    __half h0, l0, h1, l1;
                    split_h(v0, h0, l0); split_h(v1, h1, l1);
                    __half* p = Cb + (size_t)mg * (2 * RNNK) + coff(nc);
                    *(__half2*)(p)      = __halves2half2(h0, h1);
                    *(__half2*)(p + 32) = __halves2half2(l0, l1);
                }
            }
        }
    }
}

// ---------------- softmax: rows of 512 -> split fp16 alpha (interleaved-32) ----------------
__global__ void softmax_kernel(const float* __restrict__ S, const unsigned char* __restrict__ x2mask) {
    const float NEGF = -3.4e38f;
    const float2* row = (const float2*)(S + (size_t)blockIdx.x * 512);
    int b = blockIdx.x / 1536;
    const unsigned char* mk = x2mask + b * 512;
    int t = threadIdx.x;
    float2 v = row[t];
    if (mk[2 * t])     v.x = NEGF;
    if (mk[2 * t + 1]) v.y = NEGF;
    __shared__ float red[8];
    float mx = fmaxf(v.x, v.y);
#pragma unroll
    for (int o = 16; o; o >>= 1) mx = fmaxf(mx, __shfl_xor_sync(0xffffffffu, mx, o));
    if ((t & 31) == 0) red[t >> 5] = mx;
    __syncthreads();
    float M = red[0];
#pragma unroll
    for (int i = 1; i < 8; i++) M = fmaxf(M, red[i]);
    __syncthreads();
    float e0 = __expf(v.x - M), e1 = __expf(v.y - M);
    float s = e0 + e1;
#pragma unroll
    for (int o = 16; o; o >>= 1) s += __shfl_xor_sync(0xffffffffu, s, o);
    if ((t & 31) == 0) red[t >> 5] = s;
    __syncthreads();
    float tot = red[0];
#pragma unroll
    for (int i = 1; i < 8; i++) tot += red[i];
    float inv = __fdividef(1.f, tot);
    float p0 = e0 * inv, p1 = e1 * inv;
    __half h0, l0, h1, l1;
    split_h(p0, h0, l0); split_h(p1, h1, l1);
    __half* p = g_AL3 + (size_t)blockIdx.x * 1024 + coff(2 * t);
    *(__half2*)(p)      = __halves2half2(h0, h1);
    *(__half2*)(p + 32) = __halves2half2(l0, l1);
}

// ---------------- BiLSTM: fp16 Whh, zbuf publish, asym barrier + double-buffered h ------
__device__ __forceinline__ float sigf(float x) { return __fdividef(1.f, 1.f + __expf(-x)); }
__device__ __forceinline__ float tanhf_fast(float x) { return 1.f - __fdividef(2.f, __expf(2.f * x) + 1.f); }

#define LSTM_SMEM (16 * 512 * 8 + 512 * 4 + 2 * 128 * 2)

__global__ void __launch_bounds__(512, 1)
lstm_kernel(const float* __restrict__ G, float* __restrict__ out) {
    extern __shared__ char smraw[];
    uint2* Ws   = (uint2*)smraw;                       // [k4 0..15][512]
    float* zbuf = (float*)(smraw + 16 * 512 * 8);
    __half* hsH = (__half*)(smraw + 16 * 512 * 8 + 512 * 4);   // [2][128]

    const int dir = blockIdx.x & 1;
    const int b   = blockIdx.x >> 1;
    const int g   = threadIdx.x;

    const uint2* Wg = g_WhhH + (size_t)dir * 32 * 512;
    for (int i = g; i < 16 * 512; i += 512) Ws[i] = Wg[i];
    uint2 wr[16];
#pragma unroll
    for (int j = 0; j < 16; j++) wr[j] = Wg[(16 + j) * 512 + g];
    if (g < 128) hsH[g] = __float2half(0.f);           // buffer 0 = h_0
    float c = 0.f;
    __syncthreads();

    const float* gptr = G + (size_t)b * 512 * NG + dir * 512 + g;
    int trow = dir ? 511 : 0;
    const int tstep = dir ? -1 : 1;
    float gv = gptr[(size_t)trow * NG];

    const __half2 z2 = __floats2half2_rn(0.f, 0.f);

    for (int t = 0; t < 512; ++t) {
        float gcur = gv;
        if (t + 1 < 512) gv = gptr[(size_t)(trow + tstep) * NG];

        const int rb = t & 1;
        uint4 hu[16];
        const uint4* hp = (const uint4*)(hsH + rb * 128);
#pragma unroll
        for (int j = 0; j < 16; j++) hu[j] = hp[j];

        __half2 accA[4] = {z2, z2, z2, z2};
        __half2 accB[4] = {z2, z2, z2, z2};
#pragma unroll
        for (int k4 = 0; k4 < 16; k4++) {
            uint2 w = Ws[k4 * 512 + g];
            uint4 h4 = hu[k4 >> 1];
            uint32_t ha = (k4 & 1) ? h4.z : h4.x;
            uint32_t hb = (k4 & 1) ? h4.w : h4.y;
            accA[k4 & 3] = __hfma2(u2h2(w.x), u2h2(ha), accA[k4 & 3]);
            accB[k4 & 3] = __hfma2(u2h2(w.y), u2h2(hb), accB[k4 & 3]);
        }
#pragma unroll
        for (int j = 0; j < 16; j++) {
            int k4 = 16 + j;
            uint2 w = wr[j];
            uint4 h4 = hu[k4 >> 1];
            uint32_t ha = (k4 & 1) ? h4.z : h4.x;
            uint32_t hb = (k4 & 1) ? h4.w : h4.y;
            accA[j & 3] = __hfma2(u2h2(w.x), u2h2(ha), accA[j & 3]);
            accB[j & 3] = __hfma2(u2h2(w.y), u2h2(hb), accB[j & 3]);
        }
        float zsum = 0.f;
#pragma unroll
        for (int j = 0; j < 4; j++) {
            float2 fa = __half22float2(accA[j]);
            float2 fb = __half22float2(accB[j]);
            zsum += (fa.x + fa.y) + (fb.x + fb.y);
        }
        zbuf[g] = zsum + gcur;

        // asymmetric publish barrier: writers (g<128) sync, others just arrive
        if (g < 128) {
            asm volatile("bar.sync 1, 512;" ::: "memory");
            float zi = zbuf[g], zf = zbuf[g + 128], zg = zbuf[g + 256], zo = zbuf[g + 384];
            c = sigf(zf) * c + sigf(zi) * tanhf_fast(zg);
            float h = sigf(zo) * tanhf_fast(c);
            hsH[(rb ^ 1) * 128 + g] = __float2half_rn(h);
            out[((size_t)b * 512 + trow) * 256 + dir * 128 + g] = h;
        } else {
            asm volatile("bar.arrive 1, 512;" ::: "memory");
        }
        __syncthreads();   // h-publish visible before next step reads hsH[rb^1]
        trow += tstep;
    }
}

// ---------------- launch ----------------
extern "C" void kernel_launch(void* const* d_in, const int* in_sizes, int n_in,
                              void* d_out, int out_size) {
    const float* x1w  = (const float*)d_in[0];
    const float* x1a0 = (const float*)d_in[1];
    const float* x1a1 = (const float*)d_in[2];
    const float* x2w  = (const float*)d_in[3];
    const float* x2a0 = (const float*)d_in[4];
    const float* x2a1 = (const float*)d_in[5];
    const float* x2a2 = (const float*)d_in[6];
    const unsigned char* x2mask = (const unsigned char*)d_in[8];
    const float* Wattn = (const float*)d_in[9];
    const float* vattn = (const float*)d_in[10];
    const float* Wihf = (const float*)d_in[11];
    const float* Whhf = (const float*)d_in[12];
    const float* bf   = (const float*)d_in[13];
    const float* Wihb = (const float*)d_in[14];
    const float* Whhb = (const float*)d_in[15];
    const float* bb   = (const float*)d_in[16];
    float* out = (float*)d_out;

    static bool attr_done = false;
    static cudaStream_t s1 = nullptr;
    static cudaEvent_t ev_fork = nullptr, ev_join = nullptr;
    if (!attr_done) {
        cudaFuncSetAttribute(lstm_kernel, cudaFuncAttributeMaxDynamicSharedMemorySize, LSTM_SMEM);
        cudaFuncSetAttribute((const void*)hgemm<0,3>, cudaFuncAttributeMaxDynamicSharedMemorySize, HG_SMEM);
        cudaFuncSetAttribute((const void*)hgemm<1,3>, cudaFuncAttributeMaxDynamicSharedMemorySize, HG_SMEM);
        cudaFuncSetAttribute((const void*)hgemm<2,2>, cudaFuncAttributeMaxDynamicSharedMemorySize, HG_SMEM);
        cudaFuncSetAttribute((const void*)hgemm<3,2>, cudaFuncAttributeMaxDynamicSharedMemorySize, HG_SMEM);
        cudaStreamCreateWithFlags(&s1, cudaStreamNonBlocking);
        cudaEventCreateWithFlags(&ev_fork, cudaEventDisableTiming);
        cudaEventCreateWithFlags(&ev_join, cudaEventDisableTiming);
        attr_done = true;
    }

    __half *A3, *W3, *R3A, *R3B, *AL3, *X2T3, *X13, *Wih3;
    float *vbig, *S, *bias, *Gm;
    cudaGetSymbolAddress((void**)&A3,   g_A3);
    cudaGetSymbolAddress((void**)&W3,   g_W3);
    cudaGetSymbolAddress((void**)&vbig, g_vbig);
    cudaGetSymbolAddress((void**)&R3A,  g_R3A);
    cudaGetSymbolAddress((void**)&R3B,  g_R3B);
    cudaGetSymbolAddress((void**)&S,    g_S);
    cudaGetSymbolAddress((void**)&AL3,  g_AL3);
    cudaGetSymbolAddress((void**)&X2T3, g_X2T3);
    cudaGetSymbolAddress((void**)&X13,  g_X13);
    cudaGetSymbolAddress((void**)&Wih3, g_Wih3);
    cudaGetSymbolAddress((void**)&bias, g_bias);
    cudaGetSymbolAddress((void**)&Gm,   g_G);

    // main stream: preps for R, then fork side stream for independent preps
    prep_A3<<<(MR * (KPADR / 8) + 255) / 256, 256>>>(x1w, x1a0, x1a1, x2w, x2a0, x2a1);
    prep_W3<<<(NR * (KPADR / 8) + 255) / 256, 256>>>(Wattn, vattn);

    cudaEventRecord(ev_fork, 0);
    cudaStreamWaitEvent(s1, ev_fork, 0);
    prep_WhhH   <<<(2 * 32 * 512 + 255) / 256, 256, 0, s1>>>(Whhf, Whhb);
    prep_Wih3   <<<(NG * (RNNK / 8) + 255) / 256, 256, 0, s1>>>(Wihf, Wihb, bf, bb);
    prep_headX13<<<(8192 * 64 + 255) / 256, 256, 0, s1>>>(x1a0, x1a1);
    {
        dim3 grid(16, 8, 48), blk(32, 32, 1);
        prep_X2T3<<<grid, blk, 0, s1>>>(x2a0, x2a1, x2a2);
    }
    cudaEventRecord(ev_join, s1);

    // R = relu(A3 * W3^T) (+v for x2 rows): M=16384, N=768, baseK=832 -> 26 chunks, 3-pass
    {
        dim3 grid(6, 128, 1);
        hgemm<1,3><<<grid, 256, HG_SMEM>>>(A3, W3, nullptr, nullptr,
            2 * KPADR, 2 * KPADR, 0, 26,
            1, 0, 0, 0, 0, 0, 0, vbig, 8192);
    }
    // scores per (b,i): S = r1 * r2^T: M=512, N=512, baseK=256 -> 8 chunks, 3-pass
    {
        dim3 grid(4, 4, 48);
        hgemm<0,3><<<grid, 256, HG_SMEM>>>(R3A, R3B, S, nullptr,
            2 * NR, 2 * NR, 512, 8,
            3,
            (long)512 * 2 * NR, 512, (long)512 * 2 * NR, 512,
            (long)3 * 512 * 512, (long)512 * 512, nullptr, 0);
    }
    softmax_kernel<<<48 * 512, 256>>>(S, x2mask);

    // join side stream before its consumers
    cudaStreamWaitEvent(0, ev_join, 0);

    // attn per (b,i): X13[:, base 512 + i*256 ..] = alpha * x2_i^T: M=512, N=256, baseK=512 -> 16 chunks, 2-pass
    {
        dim3 grid(2, 4, 48);
        hgemm<3,2><<<grid, 256, HG_SMEM>>>(AL3, X2T3, nullptr, X13 + 1024,
            1024, 1024, 0, 16,
            3,
            (long)3 * 512 * 1024, (long)512 * 1024,
            (long)256 * 1024, (long)16 * 256 * 1024,
            (long)512 * 2 * RNNK, 512, nullptr, 0);
    }
    // g_in = X13 * Wih3^T + bias: M=8192, N=1024, baseK=1280 -> 40 chunks, 2-pass
    {
        dim3 grid(8, 64, 1);
        hgemm<2,2><<<grid, 256, HG_SMEM>>>(X13, Wih3, Gm, nullptr,
            2 * RNNK, 2 * RNNK, NG, 40,
            1, 0, 0, 0, 0, 0, 0, bias, 0);
    }
    lstm_kernel<<<32, 512, LSTM_SMEM>>>(Gm, out);
}

// round 17
// speedup vs baseline: 1.1164x; 1.0076x over previous
#include <cuda_runtime.h>
#include <cuda_fp16.h>
#include <cstdint>

typedef unsigned long long ull;

#define Bz   16
#define EMB  300
#define AH   256
#define KPADR 832              // padded 812 -> 832 (26*32)
#define NR   768               // 3*256
#define MR   16384
#define RNNK 1280
#define NG   1024
#define HH   128

// ---- scratch: split fp16, INTERLEAVED-32 storage: [hi(0:32)|lo(0:32)|hi(32:64)|lo...] ----
__device__ __align__(16) __half g_A3 [MR * (2*KPADR)];   // 16384 x 1664
__device__ __align__(16) __half g_W3 [NR * (2*KPADR)];   // 768 x 1664
__device__ float  g_vbig[NR];
__device__ __align__(16) __half g_R3A[8192 * (2*NR)];    // x1 rows: 8192 x 1536
__device__ __align__(16) __half g_R3B[8192 * (2*NR)];    // x2 rows (v-scaled)
__device__ float  g_S  [48 * 512 * 512];
__device__ __align__(16) __half g_AL3[48 * 512 * 1024];  // alpha, rows (b*3+i)*512+l
__device__ __align__(16) __half g_X2T3[48 * 256 * 1024]; // x2^T, rows (i*16+b)*256+d
__device__ __align__(16) __half g_X13[8192 * (2*RNNK)];  // X1CAT, 8192 x 2560
__device__ __align__(16) __half g_Wih3[NG * (2*RNNK)];   // 1024 x 2560
__device__ float  g_bias[NG];
__device__ float  g_G  [8192 * NG];
__device__ uint2  g_WhhH[2 * 32 * 512];         // [dir][k4][gate]: 2x half2 (fp16 Whh)

// ---- helpers ----
__device__ __forceinline__ uint32_t s2u(const void* p) {
    uint32_t a;
    asm("{ .reg .u64 t; cvta.to.shared.u64 t, %1; cvt.u32.u64 %0, t; }" : "=r"(a) : "l"(p));
    return a;
}
__device__ __forceinline__ void split_h(float v, __half& h, __half& l) {
    h = __float2half_rn(v);
    l = __float2half_rn(v - __half2float(h));
}
__device__ __forceinline__ int coff(int c) {        // interleaved-32 column map (hi; lo = +32)
    return ((c >> 5) << 6) + (c & 31);
}
__device__ __forceinline__ uint32_t swz(uint32_t off) {
    return off ^ ((off >> 3) & 0x70);
}
__device__ __forceinline__ void cp16(uint32_t dst, const void* src) {
    asm volatile("cp.async.cg.shared.global [%0], [%1], 16;" :: "r"(dst), "l"(src));
}
__device__ __forceinline__ void ldm_x4(uint32_t* r, uint32_t addr) {
    asm volatile("ldmatrix.sync.aligned.m8n8.x4.shared.b16 {%0,%1,%2,%3}, [%4];"
                 : "=r"(r[0]), "=r"(r[1]), "=r"(r[2]), "=r"(r[3]) : "r"(addr));
}
__device__ __forceinline__ void mma16816(float* c, const uint32_t* a, const uint32_t* b) {
    asm volatile(
        "mma.sync.aligned.m16n8k16.row.col.f32.f16.f16.f32 "
        "{%0,%1,%2,%3}, {%4,%5,%6,%7}, {%8,%9}, {%0,%1,%2,%3};"
        : "+f"(c[0]), "+f"(c[1]), "+f"(c[2]), "+f"(c[3])
        : "r"(a[0]), "r"(a[1]), "r"(a[2]), "r"(a[3]), "r"(b[0]), "r"(b[1]));
}
__device__ __forceinline__ __half2 u2h2(uint32_t u) {
    __half2 h; asm("mov.b32 %0, %1;" : "=r"(*(uint32_t*)&h) : "r"(u)); return h;
}
__device__ __forceinline__ uint4 pack8(const __half* v) {
    __half2 h2[4];
#pragma unroll
    for (int q = 0; q < 4; q++) h2[q] = __halves2half2(v[2*q], v[2*q+1]);
    return *(uint4*)h2;
}

// ---------------- prep kernels (vectorized: 8 elems/thread, uint4 stores) ----------------
__global__ void prep_A3(const float* __restrict__ x1w, const float* __restrict__ x1a0,
                        const float* __restrict__ x1a1, const float* __restrict__ x2w,
                        const float* __restrict__ x2a0, const float* __restrict__ x2a1) {
    int idx = blockIdx.x * 256 + threadIdx.x;
    if (idx >= MR * (KPADR / 8)) return;
    int r = idx / (KPADR / 8), c0 = (idx - r * (KPADR / 8)) * 8;
    int half = r >> 13, bl = r & 8191;
    __half hi[8], lo[8];
#pragma unroll
    for (int e = 0; e < 8; e++) {
        int c = c0 + e;
        float v = 0.f;
        if (c < 300)       v = (half ? x2w  : x1w )[(size_t)bl * EMB + c];
        else if (c < 556)  v = (half ? x2a0 : x1a0)[(size_t)bl * AH + (c - 300)];
        else if (c < 812)  v = (half ? x2a1 : x1a1)[(size_t)bl * AH + (c - 556)];
        split_h(v, hi[e], lo[e]);
    }
    __half* p = g_A3 + (size_t)r * (2 * KPADR) + ((c0 >> 5) << 6) + (c0 & 31);
    *(uint4*)p        = pack8(hi);
    *(uint4*)(p + 32) = pack8(lo);
}

__global__ void prep_W3(const float* __restrict__ Wattn, const float* __restrict__ vattn) {
    int idx = blockIdx.x * 256 + threadIdx.x;
    if (idx >= NR * (KPADR / 8)) return;
    int g = idx / (KPADR / 8), c0 = (idx - g * (KPADR / 8)) * 8;
    int i = g >> 8, a = g & 255;
    __half hi[8], lo[8];
#pragma unroll
    for (int e = 0; e < 8; e++) {
        int c = c0 + e;
        float v = (a < 250 && c < 812) ? Wattn[((size_t)(i * 250 + a)) * 812 + c] : 0.f;
        split_h(v, hi[e], lo[e]);
    }
    __half* p = g_W3 + (size_t)g * (2 * KPADR) + ((c0 >> 5) << 6) + (c0 & 31);
    *(uint4*)p        = pack8(hi);
    *(uint4*)(p + 32) = pack8(lo);
    if (idx < NR) {
        int i2 = idx >> 8, a2 = idx & 255;
        g_vbig[idx] = (a2 < 250) ? vattn[i2 * 250 + a2] : 0.f;
    }
}

__global__ void prep_Wih3(const float* __restrict__ Wf, const float* __restrict__ Wb,
                          const float* __restrict__ bf, const float* __restrict__ bb) {
    int idx = blockIdx.x * 256 + threadIdx.x;
    if (idx >= NG * (RNNK / 8)) return;
    int r = idx / (RNNK / 8), c0 = (idx - r * (RNNK / 8)) * 8;
    const float* src = (r < 512) ? Wf + (size_t)r * RNNK : Wb + (size_t)(r - 512) * RNNK;
    __half hi[8], lo[8];
#pragma unroll
    for (int e = 0; e < 8; e++) {
        split_h(src[c0 + e], hi[e], lo[e]);
    }
    __half* p = g_Wih3 + (size_t)r * (2 * RNNK) + ((c0 >> 5) << 6) + (c0 & 31);
    *(uint4*)p        = pack8(hi);
    *(uint4*)(p + 32) = pack8(lo);
    if (idx < NG) g_bias[idx] = (idx < 512) ? bf[idx] : bb[idx - 512];
}

__global__ void prep_headX13(const float* __restrict__ x1a0, const float* __restrict__ x1a1) {
    int idx = blockIdx.x * 256 + threadIdx.x;
    if (idx >= 8192 * 64) return;                   // 512 cols / 8
    int r = idx >> 6, c0 = (idx & 63) * 8;
    const float* src = (c0 < 256) ? x1a0 + (size_t)r * AH + c0
                                  : x1a1 + (size_t)r * AH + (c0 - 256);
    __half hi[8], lo[8];
#pragma unroll
    for (int e = 0; e < 8; e++) split_h(src[e], hi[e], lo[e]);
    __half* p = g_X13 + (size_t)r * (2 * RNNK) + ((c0 >> 5) << 6) + (c0 & 31);
    *(uint4*)p        = pack8(hi);
    *(uint4*)(p + 32) = pack8(lo);
}

// transpose x2_abstr_i [b][s][d] -> X2T3 rows (i*16+b)*256+d, cols s (interleaved-32)
__global__ void prep_X2T3(const float* __restrict__ a0, const float* __restrict__ a1,
                          const float* __restrict__ a2) {
    __shared__ float tile[32][33];
    int i = blockIdx.z >> 4, b = blockIdx.z & 15;
    int s0 = blockIdx.x * 32, d0 = blockIdx.y * 32;
    int tx = threadIdx.x, ty = threadIdx.y;
    const float* src = (i == 0) ? a0 : (i == 1) ? a1 : a2;
    tile[ty][tx] = src[((size_t)(b * 512 + s0 + ty)) * 256 + d0 + tx];
    __syncthreads();
    float v = tile[tx][ty];
    __half h, l; split_h(v, h, l);
    __half* p = g_X2T3 + ((size_t)((i * 16 + b) * 256 + d0 + ty)) * 1024 + s0 * 2 + tx;
    p[0] = h; p[32] = l;
}

// fp16 Whh, layout [dir][k4 0..31][gate 0..511]
__global__ void prep_WhhH(const float* __restrict__ Whhf, const float* __restrict__ Whhb) {
    int idx = blockIdx.x * 256 + threadIdx.x;
    if (idx >= 2 * 32 * 512) return;
    int d = idx >> 14, k4 = (idx >> 9) & 31, g = idx & 511;
    const float* s = d ? Whhb : Whhf;
    size_t base = (size_t)g * HH + k4 * 4;
    __half2 p0 = __floats2half2_rn(s[base],     s[base + 1]);
    __half2 p1 = __floats2half2_rn(s[base + 2], s[base + 3]);
    uint2 u;
    u.x = *(uint32_t*)&p0;
    u.y = *(uint32_t*)&p1;
    g_WhhH[idx] = u;
}

// ---------------- HMMA GEMM: grid-per-tile, split fp16, interleaved-32 storage --------
// Chunk = 32 base cols = one 128B smem row slice (hi|lo). Stage 32KB, 3 stages, 2 CTA/SM.
// NPASS=3: Ah*Bh + Al*Bh + Ah*Bl (exact).  NPASS=2: drops Ah*Bl.
// EPI: 0 scores f32 | 1 R split-out relu(+v) | 2 gin f32+bias | 3 X13 split-out | 4 f32 +=acc
#define HG_STAGE 32768
#define HG_SMEM  (3 * HG_STAGE)

template <int EPI, int NPASS>
__global__ void __launch_bounds__(256, 2)
hgemm(const __half* __restrict__ A, const __half* __restrict__ B,
      float* __restrict__ Cf, __half* __restrict__ Cb,
      int ldA, int ldB, int ldC, int nkc,
      int zdiv, long sAb, long sAi, long sBb, long sBi, long sCb, long sCi,
      const float* __restrict__ evec, int rowSplit) {
    extern __shared__ __align__(1024) char smem[];
    const uint32_t su = s2u(smem);
    const int tid = threadIdx.x, lane = tid & 31, wid = tid >> 5;

    const int z = blockIdx.z, zi = z % zdiv, zb = z / zdiv;
    A += zb * sAb + zi * sAi;
    B += zb * sBb + zi * sBi;
    if (EPI == 0 || EPI == 2 || EPI == 4) Cf += zb * sCb + zi * sCi;
    if (EPI == 3)                         Cb += zb * sCb + zi * sCi;
    const int m0 = blockIdx.y * 128, n0 = blockIdx.x * 128;
    const int r0 = tid >> 3, c16 = tid & 7;

    float acc[2][8][4];
#pragma unroll
    for (int i = 0; i < 2; i++)
#pragma unroll
        for (int j = 0; j < 8; j++)
#pragma unroll
            for (int q = 0; q < 4; q++) acc[i][j][q] = 0.f;

    const int wm = wid & 3, wn = wid >> 2;
    const int a_row = wm * 32 + (lane & 15);
    const int a_kb  = (lane >> 4) * 8;           // halves
    const int b_row = wn * 64 + ((lane >> 4) << 3) + (lane & 7);
    const int b_kb  = ((lane >> 3) & 1) * 8;     // halves

    auto issue = [&](int kc, int st) {
        const __half* Ag = A + (size_t)(m0 + r0) * ldA + kc * 64 + c16 * 8;
        const __half* Bg = B + (size_t)(n0 + r0) * ldB + kc * 64 + c16 * 8;
        uint32_t sb = su + st * HG_STAGE;
#pragma unroll
        for (int j = 0; j < 4; ++j) {
            uint32_t off = swz((r0 + 32 * j) * 128 + c16 * 16);
            cp16(sb + off,          Ag + (size_t)(32 * j) * ldA);
            cp16(sb + 16384 + off,  Bg + (size_t)(32 * j) * ldB);
        }
        asm volatile("cp.async.commit_group;" ::: "memory");
    };

    issue(0, 0);
    issue(1, 1);
    for (int kc = 0; kc < nkc; ++kc) {
        const int st = kc % 3;
        if (kc == nkc - 1)
            asm volatile("cp.async.wait_group 0;" ::: "memory");  // last chunk IS the newest group
        else
            asm volatile("cp.async.wait_group 1;" ::: "memory");
        __syncthreads();
        if (kc + 2 < nkc) issue(kc + 2, (kc + 2) % 3);
        const uint32_t sA = su + st * HG_STAGE;
        const uint32_t sB = sA + 16384;
#pragma unroll
        for (int s = 0; s < 2; ++s) {
            const uint32_t aH0 = (uint32_t)(a_row)      * 128 + (s * 16 + a_kb) * 2;
            const uint32_t aH1 = (uint32_t)(a_row + 16) * 128 + (s * 16 + a_kb) * 2;
            uint32_t ah[2][4], al[2][4], bb[4][4];
            ldm_x4(ah[0], sA + swz(aH0));
            ldm_x4(ah[1], sA + swz(aH1));
#pragma unroll
            for (int nj = 0; nj < 4; ++nj) {
                uint32_t off = (uint32_t)(b_row + nj * 16) * 128 + (s * 16 + b_kb) * 2;
                ldm_x4(bb[nj], sB + swz(off));
            }
            // pass 1: Ah * Bh
#pragma unroll
            for (int mi = 0; mi < 2; ++mi)
#pragma unroll
                for (int ni = 0; ni < 8; ++ni)
                    mma16816(acc[mi][ni], ah[mi], &bb[ni >> 1][(ni & 1) * 2]);
            // pass 2: Al * Bh
            ldm_x4(al[0], sA + swz(aH0 + 64));
            ldm_x4(al[1], sA + swz(aH1 + 64));
#pragma unroll
            for (int mi = 0; mi < 2; ++mi)
#pragma unroll
                for (int ni = 0; ni < 8; ++ni)
                    mma16816(acc[mi][ni], al[mi], &bb[ni >> 1][(ni & 1) * 2]);
            // pass 3: Ah * Bl (reuse bb regs) — exact mode only
            if (NPASS == 3) {
#pragma unroll
                for (int nj = 0; nj < 4; ++nj) {
                    uint32_t off = (uint32_t)(b_row + nj * 16) * 128 + (s * 16 + b_kb) * 2 + 64;
                    ldm_x4(bb[nj], sB + swz(off));
                }
#pragma unroll
                for (int mi = 0; mi < 2; ++mi)
#pragma unroll
                    for (int ni = 0; ni < 8; ++ni)
                        mma16816(acc[mi][ni], ah[mi], &bb[ni >> 1][(ni & 1) * 2]);
            }
        }
    }

    const int tq = lane >> 2, tr = (lane & 3) * 2;
#pragma unroll
    for (int mi = 0; mi < 2; ++mi) {
#pragma unroll
        for (int h = 0; h < 2; ++h) {
            const int mg = m0 + wm * 32 + mi * 16 + h * 8 + tq;
#pragma unroll
            for (int ni = 0; ni < 8; ++ni) {
                const int nc = n0 + wn * 64 + ni * 8 + tr;
                float v0 = acc[mi][ni][h * 2], v1 = acc[mi][ni][h * 2 + 1];
                if (EPI == 0) {
                    *(float2*)(Cf + (size_t)mg * ldC + nc) = make_float2(v0, v1);
                } else if (EPI == 2) {
                    *(float2*)(Cf + (size_t)mg * ldC + nc) =
                        make_float2(v0 + evec[nc], v1 + evec[nc + 1]);
                } else if (EPI == 4) {
                    float2* dst = (float2*)(Cf + (size_t)mg * ldC + nc);
                    float2 old = *dst;
                    *dst = make_float2(old.x + v0, old.y + v1);
                } else if (EPI == 1) {
                    const bool isB = (mg >= rowSplit);
                    v0 = fmaxf(v0, 0.f); v1 = fmaxf(v1, 0.f);
                    if (isB) { v0 *= evec[nc]; v1 *= evec[nc + 1]; }
                    __half h0, l0, h1, l1;
                    split_h(v0, h0, l0); split_h(v1, h1, l1);
                    __half* p = (isB ? g_R3B + (size_t)(mg - rowSplit) * (2 * NR)
                                     : g_R3A + (size_t)mg * (2 * NR)) + coff(nc);
                    *(__half2*)(p)      = __halves2half2(h0, h1);
                    *(__half2*)(p + 32) = __halves2half2(l0, l1);
                } else {  // EPI == 3
                    __half h0, l0, h1, l1;
                    split_h(v0, h0, l0); split_h(v1, h1, l1);
                    __half* p = Cb + (size_t)mg * (2 * RNNK) + coff(nc);
                    *(__half2*)(p)      = __halves2half2(h0, h1);
                    *(__half2*)(p + 32) = __halves2half2(l0, l1);
                }
            }
        }
    }
}

// ---------------- softmax: rows of 512 -> split fp16 alpha (interleaved-32) ----------------
__global__ void softmax_kernel(const float* __restrict__ S, const unsigned char* __restrict__ x2mask) {
    const float NEGF = -3.4e38f;
    const float2* row = (const float2*)(S + (size_t)blockIdx.x * 512);
    int b = blockIdx.x / 1536;
    const unsigned char* mk = x2mask + b * 512;
    int t = threadIdx.x;
    float2 v = row[t];
    if (mk[2 * t])     v.x = NEGF;
    if (mk[2 * t + 1]) v.y = NEGF;
    __shared__ float red[8];
    float mx = fmaxf(v.x, v.y);
#pragma unroll
    for (int o = 16; o; o >>= 1) mx = fmaxf(mx, __shfl_xor_sync(0xffffffffu, mx, o));
    if ((t & 31) == 0) red[t >> 5] = mx;
    __syncthreads();
    float M = red[0];
#pragma unroll
    for (int i = 1; i < 8; i++) M = fmaxf(M, red[i]);
    __syncthreads();
    float e0 = __expf(v.x - M), e1 = __expf(v.y - M);
    float s = e0 + e1;
#pragma unroll
    for (int o = 16; o; o >>= 1) s += __shfl_xor_sync(0xffffffffu, s, o);
    if ((t & 31) == 0) red[t >> 5] = s;
    __syncthreads();
    float tot = red[0];
#pragma unroll
    for (int i = 1; i < 8; i++) tot += red[i];
    float inv = __fdividef(1.f, tot);
    float p0 = e0 * inv, p1 = e1 * inv;
    __half h0, l0, h1, l1;
    split_h(p0, h0, l0); split_h(p1, h1, l1);
    __half* p = g_AL3 + (size_t)blockIdx.x * 1024 + coff(2 * t);
    *(__half2*)(p)      = __halves2half2(h0, h1);
    *(__half2*)(p + 32) = __halves2half2(l0, l1);
}

// ---------------- BiLSTM: fp16 Whh, zbuf publish, asym barrier + double-buffered h ------
__device__ __forceinline__ float sigf(float x) { return __fdividef(1.f, 1.f + __expf(-x)); }
__device__ __forceinline__ float tanhf_fast(float x) { return 1.f - __fdividef(2.f, __expf(2.f * x) + 1.f); }

#define LSTM_SMEM (16 * 512 * 8 + 512 * 4 + 2 * 128 * 2)

__global__ void __launch_bounds__(512, 1)
lstm_kernel(const float* __restrict__ G, float* __restrict__ out) {
    extern __shared__ char smraw[];
    uint2* Ws   = (uint2*)smraw;                       // [k4 0..15][512]
    float* zbuf = (float*)(smraw + 16 * 512 * 8);
    __half* hsH = (__half*)(smraw + 16 * 512 * 8 + 512 * 4);   // [2][128]

    const int dir = blockIdx.x & 1;
    const int b   = blockIdx.x >> 1;
    const int g   = threadIdx.x;

    const uint2* Wg = g_WhhH + (size_t)dir * 32 * 512;
    for (int i = g; i < 16 * 512; i += 512) Ws[i] = Wg[i];
    uint2 wr[16];
#pragma unroll
    for (int j = 0; j < 16; j++) wr[j] = Wg[(16 + j) * 512 + g];
    if (g < 128) hsH[g] = __float2half(0.f);           // buffer 0 = h_0
    float c = 0.f;
    __syncthreads();

    const float* gptr = G + (size_t)b * 512 * NG + dir * 512 + g;
    int trow = dir ? 511 : 0;
    const int tstep = dir ? -1 : 1;
    float gv = gptr[(size_t)trow * NG];

    const __half2 z2 = __floats2half2_rn(0.f, 0.f);

    for (int t = 0; t < 512; ++t) {
        float gcur = gv;
        if (t + 1 < 512) gv = gptr[(size_t)(trow + tstep) * NG];

        const int rb = t & 1;
        uint4 hu[16];
        const uint4* hp = (const uint4*)(hsH + rb * 128);
#pragma unroll
        for (int j = 0; j < 16; j++) hu[j] = hp[j];

        __half2 accA[4] = {z2, z2, z2, z2};
        __half2 accB[4] = {z2, z2, z2, z2};
#pragma unroll
        for (int k4 = 0; k4 < 16; k4++) {
            uint2 w = Ws[k4 * 512 + g];
            uint4 h4 = hu[k4 >> 1];
            uint32_t ha = (k4 & 1) ? h4.z : h4.x;
            uint32_t hb = (k4 & 1) ? h4.w : h4.y;
            accA[k4 & 3] = __hfma2(u2h2(w.x), u2h2(ha), accA[k4 & 3]);
            accB[k4 & 3] = __hfma2(u2h2(w.y), u2h2(hb), accB[k4 & 3]);
        }
#pragma unroll
        for (int j = 0; j < 16; j++) {
            int k4 = 16 + j;
            uint2 w = wr[j];
            uint4 h4 = hu[k4 >> 1];
            uint32_t ha = (k4 & 1) ? h4.z : h4.x;
            uint32_t hb = (k4 & 1) ? h4.w : h4.y;
            accA[j & 3] = __hfma2(u2h2(w.x), u2h2(ha), accA[j & 3]);
            accB[j & 3] = __hfma2(u2h2(w.y), u2h2(hb), accB[j & 3]);
        }
        float zsum = 0.f;
#pragma unroll
        for (int j = 0; j < 4; j++) {
            float2 fa = __half22float2(accA[j]);
            float2 fb = __half22float2(accB[j]);
            zsum += (fa.x + fa.y) + (fb.x + fb.y);
        }
        zbuf[g] = zsum + gcur;

        // asymmetric publish barrier: writers (g<128) sync, others just arrive
        if (g < 128) {
            asm volatile("bar.sync 1, 512;" ::: "memory");
            float zi = zbuf[g], zf = zbuf[g + 128], zg = zbuf[g + 256], zo = zbuf[g + 384];
            c = sigf(zf) * c + sigf(zi) * tanhf_fast(zg);
            float h = sigf(zo) * tanhf_fast(c);
            hsH[(rb ^ 1) * 128 + g] = __float2half_rn(h);
            out[((size_t)b * 512 + trow) * 256 + dir * 128 + g] = h;
        } else {
            asm volatile("bar.arrive 1, 512;" ::: "memory");
        }
        __syncthreads();   // h-publish visible before next step reads hsH[rb^1]
        trow += tstep;
    }
}

// ---------------- launch ----------------
extern "C" void kernel_launch(void* const* d_in, const int* in_sizes, int n_in,
                              void* d_out, int out_size) {
    const float* x1w  = (const float*)d_in[0];
    const float* x1a0 = (const float*)d_in[1];
    const float* x1a1 = (const float*)d_in[2];
    const float* x2w  = (const float*)d_in[3];
    const float* x2a0 = (const float*)d_in[4];
    const float* x2a1 = (const float*)d_in[5];
    const float* x2a2 = (const float*)d_in[6];
    const unsigned char* x2mask = (const unsigned char*)d_in[8];
    const float* Wattn = (const float*)d_in[9];
    const float* vattn = (const float*)d_in[10];
    const float* Wihf = (const float*)d_in[11];
    const float* Whhf = (const float*)d_in[12];
    const float* bf   = (const float*)d_in[13];
    const float* Wihb = (const float*)d_in[14];
    const float* Whhb = (const float*)d_in[15];
    const float* bb   = (const float*)d_in[16];
    float* out = (float*)d_out;

    static bool attr_done = false;
    static cudaStream_t s1 = nullptr;
    static cudaEvent_t ev_fork = nullptr, ev_join = nullptr;
    if (!attr_done) {
        cudaFuncSetAttribute(lstm_kernel, cudaFuncAttributeMaxDynamicSharedMemorySize, LSTM_SMEM);
        cudaFuncSetAttribute((const void*)hgemm<0,3>, cudaFuncAttributeMaxDynamicSharedMemorySize, HG_SMEM);
        cudaFuncSetAttribute((const void*)hgemm<1,3>, cudaFuncAttributeMaxDynamicSharedMemorySize, HG_SMEM);
        cudaFuncSetAttribute((const void*)hgemm<2,2>, cudaFuncAttributeMaxDynamicSharedMemorySize, HG_SMEM);
        cudaFuncSetAttribute((const void*)hgemm<3,2>, cudaFuncAttributeMaxDynamicSharedMemorySize, HG_SMEM);
        cudaFuncSetAttribute((const void*)hgemm<4,2>, cudaFuncAttributeMaxDynamicSharedMemorySize, HG_SMEM);
        cudaStreamCreateWithFlags(&s1, cudaStreamNonBlocking);
        cudaEventCreateWithFlags(&ev_fork, cudaEventDisableTiming);
        cudaEventCreateWithFlags(&ev_join, cudaEventDisableTiming);
        attr_done = true;
    }

    __half *A3, *W3, *R3A, *R3B, *AL3, *X2T3, *X13, *Wih3;
    float *vbig, *S, *bias, *Gm;
    cudaGetSymbolAddress((void**)&A3,   g_A3);
    cudaGetSymbolAddress((void**)&W3,   g_W3);
    cudaGetSymbolAddress((void**)&vbig, g_vbig);
    cudaGetSymbolAddress((void**)&R3A,  g_R3A);
    cudaGetSymbolAddress((void**)&R3B,  g_R3B);
    cudaGetSymbolAddress((void**)&S,    g_S);
    cudaGetSymbolAddress((void**)&AL3,  g_AL3);
    cudaGetSymbolAddress((void**)&X2T3, g_X2T3);
    cudaGetSymbolAddress((void**)&X13,  g_X13);
    cudaGetSymbolAddress((void**)&Wih3, g_Wih3);
    cudaGetSymbolAddress((void**)&bias, g_bias);
    cudaGetSymbolAddress((void**)&Gm,   g_G);

    // main stream: preps for R, then fork side stream
    prep_A3<<<(MR * (KPADR / 8) + 255) / 256, 256>>>(x1w, x1a0, x1a1, x2w, x2a0, x2a1);
    prep_W3<<<(NR * (KPADR / 8) + 255) / 256, 256>>>(Wattn, vattn);

    cudaEventRecord(ev_fork, 0);
    cudaStreamWaitEvent(s1, ev_fork, 0);
    prep_WhhH   <<<(2 * 32 * 512 + 255) / 256, 256, 0, s1>>>(Whhf, Whhb);
    prep_Wih3   <<<(NG * (RNNK / 8) + 255) / 256, 256, 0, s1>>>(Wihf, Wihb, bf, bb);
    prep_headX13<<<(8192 * 64 + 255) / 256, 256, 0, s1>>>(x1a0, x1a1);
    {
        dim3 grid(16, 8, 48), blk(32, 32, 1);
        prep_X2T3<<<grid, blk, 0, s1>>>(x2a0, x2a1, x2a2);
    }
    // gin part1 on side stream: Gm = X13[:, 0:512] * Wih3[:, 0:512]^T + bias (16 chunks, 2-pass)
    {
        dim3 grid(8, 64, 1);
        hgemm<2,2><<<grid, 256, HG_SMEM, s1>>>(X13, Wih3, Gm, nullptr,
            2 * RNNK, 2 * RNNK, NG, 16,
            1, 0, 0, 0, 0, 0, 0, bias, 0);
    }
    cudaEventRecord(ev_join, s1);

    // R = relu(A3 * W3^T) (+v for x2 rows): M=16384, N=768, baseK=832 -> 26 chunks, 3-pass
    {
        dim3 grid(6, 128, 1);
        hgemm<1,3><<<grid, 256, HG_SMEM>>>(A3, W3, nullptr, nullptr,
            2 * KPADR, 2 * KPADR, 0, 26,
            1, 0, 0, 0, 0, 0, 0, vbig, 8192);
    }
    // scores per (b,i): S = r1 * r2^T: M=512, N=512, baseK=256 -> 8 chunks, 3-pass
    {
        dim3 grid(4, 4, 48);
        hgemm<0,3><<<grid, 256, HG_SMEM>>>(R3A, R3B, S, nullptr,
            2 * NR, 2 * NR, 512, 8,
            3,
            (long)512 * 2 * NR, 512, (long)512 * 2 * NR, 512,
            (long)3 * 512 * 512, (long)512 * 512, nullptr, 0);
    }
    softmax_kernel<<<48 * 512, 256>>>(S, x2mask);

    // join side stream before its consumers (attn needs X2T3/AL3... and gin-part2 needs part1)
    cudaStreamWaitEvent(0, ev_join, 0);

    // attn per (b,i): X13[:, base 512 + i*256 ..] = alpha * x2_i^T: M=512, N=256, baseK=512 -> 16 chunks, 2-pass
    {
        dim3 grid(2, 4, 48);
        hgemm<3,2><<<grid, 256, HG_SMEM>>>(AL3, X2T3, nullptr, X13 + 1024,
            1024, 1024, 0, 16,
            3,
            (long)3 * 512 * 1024, (long)512 * 1024,
            (long)256 * 1024, (long)16 * 256 * 1024,
            (long)512 * 2 * RNNK, 512, nullptr, 0);
    }
    // gin part2: Gm += X13[:, 512:1280] * Wih3[:, 512:1280]^T (24 chunks, 2-pass, accumulate)
    // column 512 starts at storage half-offset coff(512) = 1024
    {
        dim3 grid(8, 64, 1);
        hgemm<4,2><<<grid, 256, HG_SMEM>>>(X13 + 1024, Wih3 + 1024, Gm, nullptr,
            2 * RNNK, 2 * RNNK, NG, 24,
            1, 0, 0, 0, 0, 0, 0, nullptr, 0);
    }
    lstm_kernel<<<32, 512, LSTM_SMEM>>>(Gm, out);
}